// round 6
// baseline (speedup 1.0000x reference)
#include <cuda_runtime.h>
#include <cuda_bf16.h>
#include <cstdint>
#include <math.h>

#define SSZ 1024
#define HSZ 8
#define BHZ 64
#define MT  8192
typedef __nv_bfloat16 bf;

// ---------------- scratch (device globals) ----------------
__device__ __align__(16) bf    g_xc[3][(size_t)MT * 3072];      // split acts (hi,hi,lo)
__device__ __align__(16) bf    g_wc[4][(size_t)1024 * 3072];    // W^T split (hi,lo,hi): v,k,q,m
__device__ __align__(16) bf    g_wgc[2][(size_t)128 * 384];     // WgX^T, WgY^T split (hi,lo,hi)
__device__ __align__(16) float g_kh[(size_t)BHZ * SSZ * 128];
__device__ __align__(16) float g_qh[(size_t)BHZ * SSZ * 128];
__device__ __align__(16) bf    g_khc[(size_t)BHZ * SSZ * 384];  // (hi,hi,lo)
__device__ __align__(16) bf    g_qhc[(size_t)BHZ * SSZ * 384];
__device__ __align__(16) float g_gx[(size_t)BHZ * SSZ * 128];
__device__ __align__(16) float g_gy[(size_t)BHZ * SSZ * 128];
__device__ __align__(16) bf    g_kgc[(size_t)BHZ * SSZ * 384];  // gated k (hi,lo,hi)  [B side]
__device__ __align__(16) bf    g_qgc[(size_t)BHZ * SSZ * 384];  // gated q (hi,hi,lo)  [A side]
__device__ __align__(16) bf    g_vtc[(size_t)BHZ * 128 * 3072]; // v^T per head (hi,lo,hi)
__device__ __align__(16) float g_sc[(size_t)BHZ * SSZ * SSZ];
__device__ __align__(16) bf    g_attc[(size_t)BHZ * SSZ * 3072];// att (hi,hi,lo)
__device__ __align__(16) bf    g_ctxc[(size_t)MT * 3072];       // ctx (hi,hi,lo)

// ---------------- helpers ----------------
__device__ __forceinline__ uint32_t smem_u32(const void* p) {
    uint32_t a;
    asm("{ .reg .u64 t; cvta.to.shared.u64 t, %1; cvt.u32.u64 %0, t; }" : "=r"(a) : "l"(p));
    return a;
}
__device__ __forceinline__ uint32_t sw128(uint32_t o) { return o ^ ((o >> 3) & 0x70); }
__device__ __forceinline__ void split_bf(float v, bf& hi, bf& lo) {
    hi = __float2bfloat16(v);
    lo = __float2bfloat16(v - __bfloat162float(hi));
}

// ---------------- mma.sync GEMM: C(128x128)=A[m][K']*B[n][K']^T ----------------
struct GArgs {
    const bf *A, *B;
    long lda, ldb, bsA, bsB;
    int K;
    const float* bias;
    const unsigned char* mask;
    float* of;
    bf* oc;
};

// MODE: 0=projV(transposed split) 1=projKQ(f32+split) 2=gate(f32) 3=scores 4=attV(split) 5=final
template<int MODE>
__global__ __launch_bounds__(256) void tc_gemm(GArgs g)
{
    extern __shared__ __align__(16) char smt[];
    const uint32_t smbase = smem_u32(smt);
    const int t = threadIdx.x;
    const int lane = t & 31, wid = t >> 5;
    const int warp_m = wid >> 2, warp_n = wid & 3;

    const int m0 = blockIdx.x * 128;
    const int n0 = blockIdx.y * 128;
    const int bz = blockIdx.z;
    const bf* Ab = g.A + (size_t)bz * g.bsA + (size_t)m0 * g.lda;
    const bf* Bb = g.B + (size_t)bz * g.bsB + (size_t)n0 * g.ldb;

    float acc[4][4][4];
#pragma unroll
    for (int i = 0; i < 4; i++)
#pragma unroll
        for (int j = 0; j < 4; j++)
#pragma unroll
            for (int c = 0; c < 4; c++) acc[i][j][c] = 0.f;

    const int nch = g.K >> 6;

    // 3 smem buffers of 32KB (A 16KB + B 16KB); 2 chunks prefetched ahead.
#define PREFETCH(i)                                                              \
    {                                                                            \
        const bf* Ap = Ab + (i) * 64;                                            \
        const bf* Bp = Bb + (i) * 64;                                            \
        const uint32_t sA = smbase + ((i) % 3) * 32768;                          \
        const uint32_t sB = sA + 16384;                                          \
        _Pragma("unroll")                                                        \
        for (int r = 0; r < 4; r++) {                                            \
            const int it = t + r * 256;                                          \
            const int row = it >> 3, seg = it & 7;                               \
            const uint32_t da = sA + sw128(row * 128 + seg * 16);                \
            const bf* pa = Ap + (size_t)row * g.lda + seg * 8;                   \
            asm volatile("cp.async.cg.shared.global [%0], [%1], 16;" :: "r"(da), "l"(pa)); \
            const uint32_t db = sB + sw128(row * 128 + seg * 16);                \
            const bf* pb = Bp + (size_t)row * g.ldb + seg * 8;                   \
            asm volatile("cp.async.cg.shared.global [%0], [%1], 16;" :: "r"(db), "l"(pb)); \
        }                                                                        \
    }

    PREFETCH(0);
    asm volatile("cp.async.commit_group;" ::: "memory");
    if (nch > 1) PREFETCH(1);
    asm volatile("cp.async.commit_group;" ::: "memory");

    for (int i = 0; i < nch; i++) {
        asm volatile("cp.async.wait_group 1;" ::: "memory");
        __syncthreads();                       // buf i ready; all warps done with buf (i+2)%3
        if (i + 2 < nch) PREFETCH(i + 2);      // overwrite buf computed at iter i-1
        asm volatile("cp.async.commit_group;" ::: "memory");

        const uint32_t sA = smbase + (i % 3) * 32768;
        const uint32_t sB = sA + 16384;
#pragma unroll
        for (int ks = 0; ks < 4; ks++) {
            const int kb = ks * 32;   // byte offset of this k16 within the 128B row
            uint32_t a[4][4], b[4][2];
#pragma unroll
            for (int mi = 0; mi < 4; mi++) {
                const uint32_t addr = sA + sw128((warp_m * 64 + mi * 16 + (lane & 15)) * 128
                                                 + kb + (lane >> 4) * 16);
                asm volatile("ldmatrix.sync.aligned.m8n8.x4.shared.b16 {%0,%1,%2,%3}, [%4];"
                    : "=r"(a[mi][0]), "=r"(a[mi][1]), "=r"(a[mi][2]), "=r"(a[mi][3]) : "r"(addr));
            }
#pragma unroll
            for (int jp = 0; jp < 2; jp++) {
                const uint32_t addr = sB + sw128((warp_n * 32 + jp * 16 + ((lane >> 4) & 1) * 8
                                                  + (lane & 7)) * 128
                                                 + kb + ((lane >> 3) & 1) * 16);
                asm volatile("ldmatrix.sync.aligned.m8n8.x4.shared.b16 {%0,%1,%2,%3}, [%4];"
                    : "=r"(b[jp * 2][0]), "=r"(b[jp * 2][1]),
                      "=r"(b[jp * 2 + 1][0]), "=r"(b[jp * 2 + 1][1]) : "r"(addr));
            }
#pragma unroll
            for (int mi = 0; mi < 4; mi++)
#pragma unroll
                for (int nj = 0; nj < 4; nj++)
                    asm volatile(
                        "mma.sync.aligned.m16n8k16.row.col.f32.bf16.bf16.f32 "
                        "{%0,%1,%2,%3}, {%4,%5,%6,%7}, {%8,%9}, {%0,%1,%2,%3};"
                        : "+f"(acc[mi][nj][0]), "+f"(acc[mi][nj][1]),
                          "+f"(acc[mi][nj][2]), "+f"(acc[mi][nj][3])
                        : "r"(a[mi][0]), "r"(a[mi][1]), "r"(a[mi][2]), "r"(a[mi][3]),
                          "r"(b[nj][0]), "r"(b[nj][1]));
        }
    }
    asm volatile("cp.async.wait_group 0;" ::: "memory");

    // ---------------- epilogue: 4 col-blocks of 32 through smem staging ----------------
    float* stg = (float*)smt;   // 128 x 33 fp32
    for (int cb = 0; cb < 4; cb++) {
        __syncthreads();
        if (warp_n == cb) {
#pragma unroll
            for (int mi = 0; mi < 4; mi++)
#pragma unroll
                for (int nj = 0; nj < 4; nj++) {
                    const int r  = warp_m * 64 + mi * 16 + (lane >> 2);
                    const int cc = nj * 8 + (lane & 3) * 2;
                    stg[r * 33 + cc]           = acc[mi][nj][0];
                    stg[r * 33 + cc + 1]       = acc[mi][nj][1];
                    stg[(r + 8) * 33 + cc]     = acc[mi][nj][2];
                    stg[(r + 8) * 33 + cc + 1] = acc[mi][nj][3];
                }
        }
        __syncthreads();

        if (MODE == 0) {
            // v^T: per-head [bh][d][3S] (hi,lo,hi)
            const int dloc = t & 31, soff = (t >> 5) * 16;
            const int b = m0 >> 10, h = blockIdx.y, d = cb * 32 + dloc;
            const int scol = (m0 & 1023) + soff;
            bf hi16[16], lo16[16];
#pragma unroll
            for (int i2 = 0; i2 < 16; i2++) {
                float v = stg[(soff + i2) * 33 + dloc] + g.bias[n0 + d];
                split_bf(v, hi16[i2], lo16[i2]);
            }
            bf* dst = g.oc + ((size_t)(b * HSZ + h) * 128 + d) * 3072 + scol;
            uint4* hv = (uint4*)hi16; uint4* lv = (uint4*)lo16;
            *(uint4*)(dst) = hv[0];          *(uint4*)(dst + 8) = hv[1];
            *(uint4*)(dst + 1024) = lv[0];   *(uint4*)(dst + 1032) = lv[1];
            *(uint4*)(dst + 2048) = hv[0];   *(uint4*)(dst + 2056) = hv[1];
        } else {
            const int row = t >> 1, c0 = (t & 1) * 16;
            const float* sr = stg + row * 33 + c0;
            if (MODE == 1) {
                const int h = blockIdx.y, m = m0 + row, b = m >> 10, s = m & 1023;
                const int d0 = cb * 32 + c0;
                const size_t ri = (size_t)(b * HSZ + h) * SSZ + s;
                float* fd = g.of + ri * 128 + d0;
                bf* cd = g.oc + ri * 384 + d0;
#pragma unroll
                for (int c = 0; c < 16; c++) {
                    float v = sr[c] + g.bias[n0 + d0 + c];
                    fd[c] = v;
                    bf hi, lo; split_bf(v, hi, lo);
                    cd[c] = hi; cd[128 + c] = hi; cd[256 + c] = lo;
                }
            } else if (MODE == 2) {
                float* fd = g.of + (size_t)(m0 + row) * 128 + cb * 32 + c0;
#pragma unroll
                for (int c = 0; c < 16; c += 4) {
                    float4 w;
                    w.x = sr[c]     + g.bias[cb * 32 + c0 + c];
                    w.y = sr[c + 1] + g.bias[cb * 32 + c0 + c + 1];
                    w.z = sr[c + 2] + g.bias[cb * 32 + c0 + c + 2];
                    w.w = sr[c + 3] + g.bias[cb * 32 + c0 + c + 3];
                    *(float4*)(fd + c) = w;
                }
            } else if (MODE == 3) {
                const int nt = n0 + cb * 32 + c0;
                float* fd = g.of + ((size_t)bz * SSZ + m0 + row) * SSZ + nt;
                const unsigned char* mk = g.mask + (size_t)(bz >> 3) * SSZ + nt;
                const float sc = 0.08838834764831845f;
#pragma unroll
                for (int c = 0; c < 16; c += 4) {
                    float4 w;
                    w.x = mk[c]     ? -1e9f : sr[c]     * sc;
                    w.y = mk[c + 1] ? -1e9f : sr[c + 1] * sc;
                    w.z = mk[c + 2] ? -1e9f : sr[c + 2] * sc;
                    w.w = mk[c + 3] ? -1e9f : sr[c + 3] * sc;
                    *(float4*)(fd + c) = w;
                }
            } else if (MODE == 4) {
                const int b = bz >> 3, h = bz & 7, n = cb * 32 + c0;
                bf* cd = g.oc + ((size_t)b * SSZ + m0 + row) * 3072 + h * 128 + n;
                bf hi16[16], lo16[16];
#pragma unroll
                for (int c = 0; c < 16; c++) split_bf(sr[c], hi16[c], lo16[c]);
                uint4* hv = (uint4*)hi16; uint4* lv = (uint4*)lo16;
                *(uint4*)(cd) = hv[0];          *(uint4*)(cd + 8) = hv[1];
                *(uint4*)(cd + 1024) = hv[0];   *(uint4*)(cd + 1032) = hv[1];
                *(uint4*)(cd + 2048) = lv[0];   *(uint4*)(cd + 2056) = lv[1];
            } else {
                const int nt = n0 + cb * 32 + c0;
                float* fd = g.of + (size_t)(m0 + row) * 1024 + nt;
#pragma unroll
                for (int c = 0; c < 16; c += 4) {
                    float4 w;
                    w.x = sr[c]     + g.bias[nt + c];
                    w.y = sr[c + 1] + g.bias[nt + c + 1];
                    w.z = sr[c + 2] + g.bias[nt + c + 2];
                    w.w = sr[c + 3] + g.bias[nt + c + 3];
                    *(float4*)(fd + c) = w;
                }
            }
        }
    }
}

// ---------------- prep kernels ----------------
__global__ __launch_bounds__(256) void split_act(const float* v, const float* k, const float* q)
{
    const float* s = blockIdx.z == 0 ? v : blockIdx.z == 1 ? k : q;
    bf* dst = g_xc[blockIdx.z];
    const size_t i = ((size_t)blockIdx.x * 256 + threadIdx.x) * 4;
    const size_t row = i >> 10, col = i & 1023;
    float4 x = *(const float4*)(s + i);
    bf h[4], l[4];
    split_bf(x.x, h[0], l[0]); split_bf(x.y, h[1], l[1]);
    split_bf(x.z, h[2], l[2]); split_bf(x.w, h[3], l[3]);
    bf* d = dst + row * 3072 + col;
    *(uint2*)(d) = *(uint2*)h;
    *(uint2*)(d + 1024) = *(uint2*)h;
    *(uint2*)(d + 2048) = *(uint2*)l;
}

__global__ void wsplit(const float* W, bf* Wc, int K, int N)
{
    __shared__ float sm[32][33];
    const int k0 = blockIdx.y * 32, n0 = blockIdx.x * 32;
    for (int r = threadIdx.y; r < 32; r += 8)
        sm[r][threadIdx.x] = W[(size_t)(k0 + r) * N + n0 + threadIdx.x];
    __syncthreads();
    for (int r = threadIdx.y; r < 32; r += 8) {
        bf hi, lo; split_bf(sm[threadIdx.x][r], hi, lo);
        bf* d = Wc + (size_t)(n0 + r) * 3 * K + k0 + threadIdx.x;
        d[0] = hi; d[K] = lo; d[2 * K] = hi;
    }
}

__global__ __launch_bounds__(128) void gate_apply(const float* Wg2, const float* bg2)
{
    const size_t row = blockIdx.x;
    const int d = threadIdx.x;
    const size_t o = row * 128 + d;
    float tv = g_gx[o] * g_gy[o];
    float s0 = tv * Wg2[d * 2], s1 = tv * Wg2[d * 2 + 1];
    const int lane = d & 31, w = d >> 5;
#pragma unroll
    for (int off = 16; off; off >>= 1) {
        s0 += __shfl_xor_sync(0xFFFFFFFFu, s0, off);
        s1 += __shfl_xor_sync(0xFFFFFFFFu, s1, off);
    }
    __shared__ float r0[4], r1[4];
    if (lane == 0) { r0[w] = s0; r1[w] = s1; }
    __syncthreads();
    float t0 = r0[0] + r0[1] + r0[2] + r0[3];
    float t1 = r1[0] + r1[1] + r1[2] + r1[3];
    float gk = 1.f / (1.f + __expf(-(t0 + bg2[0])));
    float gq = 1.f / (1.f + __expf(-(t1 + bg2[1])));
    bf hi, lo;
    split_bf(g_kh[o] * gk, hi, lo);
    bf* kd = g_kgc + row * 384 + d;                       // (hi,lo,hi)
    kd[0] = hi; kd[128] = lo; kd[256] = hi;
    split_bf(g_qh[o] * gq, hi, lo);
    bf* qd = g_qgc + row * 384 + d;                       // (hi,hi,lo)
    qd[0] = hi; qd[128] = hi; qd[256] = lo;
}

__global__ __launch_bounds__(256) void softmax_kernel()
{
    const size_t row = blockIdx.x;
    const float4 vv = *(const float4*)(g_sc + row * SSZ + threadIdx.x * 4);
    float m = fmaxf(fmaxf(vv.x, vv.y), fmaxf(vv.z, vv.w));
    const int lane = threadIdx.x & 31, w = threadIdx.x >> 5;
#pragma unroll
    for (int off = 16; off; off >>= 1) m = fmaxf(m, __shfl_xor_sync(0xFFFFFFFFu, m, off));
    __shared__ float sm[8], ssum[8];
    if (lane == 0) sm[w] = m;
    __syncthreads();
    m = sm[0];
#pragma unroll
    for (int i = 1; i < 8; i++) m = fmaxf(m, sm[i]);
    float4 e;
    e.x = __expf(vv.x - m); e.y = __expf(vv.y - m);
    e.z = __expf(vv.z - m); e.w = __expf(vv.w - m);
    float s = e.x + e.y + e.z + e.w;
#pragma unroll
    for (int off = 16; off; off >>= 1) s += __shfl_xor_sync(0xFFFFFFFFu, s, off);
    if (lane == 0) ssum[w] = s;
    __syncthreads();
    s = ssum[0] + ssum[1] + ssum[2] + ssum[3] + ssum[4] + ssum[5] + ssum[6] + ssum[7];
    const float inv = 1.f / s;
    bf h[4], l[4];
    split_bf(e.x * inv, h[0], l[0]); split_bf(e.y * inv, h[1], l[1]);
    split_bf(e.z * inv, h[2], l[2]); split_bf(e.w * inv, h[3], l[3]);
    bf* d = g_attc + row * 3072 + threadIdx.x * 4;        // (hi,hi,lo)
    *(uint2*)(d) = *(uint2*)h;
    *(uint2*)(d + 1024) = *(uint2*)h;
    *(uint2*)(d + 2048) = *(uint2*)l;
}

// ---------------- launch ----------------
#define TCSMEM 98304

extern "C" void kernel_launch(void* const* d_in, const int* in_sizes, int n_in,
                              void* d_out, int out_size)
{
    (void)in_sizes; (void)n_in; (void)out_size;
    const float* v  = (const float*)d_in[0];
    const float* k  = (const float*)d_in[1];
    const float* q  = (const float*)d_in[2];
    const unsigned char* mask = (const unsigned char*)d_in[3];
    const float* Wv = (const float*)d_in[4];  const float* bv = (const float*)d_in[5];
    const float* Wk = (const float*)d_in[6];  const float* bk = (const float*)d_in[7];
    const float* Wq = (const float*)d_in[8];  const float* bq = (const float*)d_in[9];
    const float* Wm = (const float*)d_in[10]; const float* bm = (const float*)d_in[11];
    const float* WgX = (const float*)d_in[12]; const float* bgX = (const float*)d_in[13];
    const float* WgY = (const float*)d_in[14]; const float* bgY = (const float*)d_in[15];
    const float* Wg2 = (const float*)d_in[16]; const float* bg2 = (const float*)d_in[17];
    float* outp = (float*)d_out;

    cudaFuncSetAttribute(tc_gemm<0>, cudaFuncAttributeMaxDynamicSharedMemorySize, TCSMEM);
    cudaFuncSetAttribute(tc_gemm<1>, cudaFuncAttributeMaxDynamicSharedMemorySize, TCSMEM);
    cudaFuncSetAttribute(tc_gemm<2>, cudaFuncAttributeMaxDynamicSharedMemorySize, TCSMEM);
    cudaFuncSetAttribute(tc_gemm<3>, cudaFuncAttributeMaxDynamicSharedMemorySize, TCSMEM);
    cudaFuncSetAttribute(tc_gemm<4>, cudaFuncAttributeMaxDynamicSharedMemorySize, TCSMEM);
    cudaFuncSetAttribute(tc_gemm<5>, cudaFuncAttributeMaxDynamicSharedMemorySize, TCSMEM);

    bf* wc0; bf* wc1; bf* wc2; bf* wc3; bf* wg0; bf* wg1;
    bf* xc0; bf* xc1; bf* xc2;
    cudaGetSymbolAddress((void**)&wc0, g_wc);  wc1 = wc0 + (size_t)1024 * 3072;
    wc2 = wc1 + (size_t)1024 * 3072; wc3 = wc2 + (size_t)1024 * 3072;
    cudaGetSymbolAddress((void**)&wg0, g_wgc); wg1 = wg0 + (size_t)128 * 384;
    cudaGetSymbolAddress((void**)&xc0, g_xc);  xc1 = xc0 + (size_t)MT * 3072; xc2 = xc1 + (size_t)MT * 3072;
    float *kh, *qh, *gx, *gy, *sc;
    bf *khc, *qhc, *kgc, *qgc, *vtc, *attc, *ctxc;
    cudaGetSymbolAddress((void**)&kh, g_kh);   cudaGetSymbolAddress((void**)&qh, g_qh);
    cudaGetSymbolAddress((void**)&gx, g_gx);   cudaGetSymbolAddress((void**)&gy, g_gy);
    cudaGetSymbolAddress((void**)&sc, g_sc);
    cudaGetSymbolAddress((void**)&khc, g_khc); cudaGetSymbolAddress((void**)&qhc, g_qhc);
    cudaGetSymbolAddress((void**)&kgc, g_kgc); cudaGetSymbolAddress((void**)&qgc, g_qgc);
    cudaGetSymbolAddress((void**)&vtc, g_vtc); cudaGetSymbolAddress((void**)&attc, g_attc);
    cudaGetSymbolAddress((void**)&ctxc, g_ctxc);

    split_act<<<dim3(8192, 1, 3), 256>>>(v, k, q);
    wsplit<<<dim3(32, 32), dim3(32, 8)>>>(Wv, wc0, 1024, 1024);
    wsplit<<<dim3(32, 32), dim3(32, 8)>>>(Wk, wc1, 1024, 1024);
    wsplit<<<dim3(32, 32), dim3(32, 8)>>>(Wq, wc2, 1024, 1024);
    wsplit<<<dim3(32, 32), dim3(32, 8)>>>(Wm, wc3, 1024, 1024);
    wsplit<<<dim3(4, 4),   dim3(32, 8)>>>(WgX, wg0, 128, 128);
    wsplit<<<dim3(4, 4),   dim3(32, 8)>>>(WgY, wg1, 128, 128);

    GArgs a = {};
    // proj V -> vtc
    a.A = xc0; a.B = wc0; a.lda = 3072; a.ldb = 3072; a.bsA = 0; a.bsB = 0;
    a.K = 3072; a.bias = bv; a.oc = vtc;
    tc_gemm<0><<<dim3(64, 8, 1), 256, TCSMEM>>>(a);
    // proj K -> kh + khc
    a.B = wc1; a.bias = bk; a.of = kh; a.oc = khc; a.A = xc1;
    tc_gemm<1><<<dim3(64, 8, 1), 256, TCSMEM>>>(a);
    // proj Q -> qh + qhc
    a.B = wc2; a.bias = bq; a.of = qh; a.oc = qhc; a.A = xc2;
    tc_gemm<1><<<dim3(64, 8, 1), 256, TCSMEM>>>(a);
    // gate X / Y
    a.A = khc; a.B = wg0; a.lda = 384; a.ldb = 384; a.K = 384; a.bias = bgX; a.of = gx; a.oc = nullptr;
    tc_gemm<2><<<dim3(512, 1, 1), 256, TCSMEM>>>(a);
    a.A = qhc; a.B = wg1; a.bias = bgY; a.of = gy;
    tc_gemm<2><<<dim3(512, 1, 1), 256, TCSMEM>>>(a);

    gate_apply<<<BHZ * SSZ, 128>>>(Wg2, bg2);

    // scores
    a.A = qgc; a.B = kgc; a.lda = 384; a.ldb = 384; a.bsA = (long)SSZ * 384; a.bsB = (long)SSZ * 384;
    a.K = 384; a.mask = mask; a.of = sc; a.bias = nullptr;
    tc_gemm<3><<<dim3(8, 8, BHZ), 256, TCSMEM>>>(a);

    softmax_kernel<<<BHZ * SSZ, 256>>>();

    // attV -> ctxc
    a.A = attc; a.B = vtc; a.lda = 3072; a.ldb = 3072;
    a.bsA = (long)SSZ * 3072; a.bsB = (long)128 * 3072;
    a.K = 3072; a.mask = nullptr; a.of = nullptr; a.oc = ctxc;
    tc_gemm<4><<<dim3(8, 1, BHZ), 256, TCSMEM>>>(a);

    // final
    a.A = ctxc; a.B = wc3; a.bsA = 0; a.bsB = 0; a.bias = bm; a.of = outp; a.oc = nullptr;
    tc_gemm<5><<<dim3(64, 8, 1), 256, TCSMEM>>>(a);
}

// round 7
// speedup vs baseline: 1.0671x; 1.0671x over previous
#include <cuda_runtime.h>
#include <cuda_bf16.h>
#include <cstdint>
#include <math.h>

#define SSZ 1024
#define HSZ 8
#define BHZ 64
#define MT  8192
typedef __nv_bfloat16 bf;

// ---------------- scratch (device globals) ----------------
__device__ __align__(16) bf    g_xc[3][(size_t)MT * 3072];      // split acts (hi,hi,lo)
__device__ __align__(16) bf    g_wc[4][(size_t)1024 * 3072];    // W^T split (hi,lo,hi): v,k,q,m
__device__ __align__(16) bf    g_wgc[2][(size_t)128 * 384];     // WgX^T, WgY^T split (hi,lo,hi)
__device__ __align__(16) float g_kh[(size_t)BHZ * SSZ * 128];
__device__ __align__(16) float g_qh[(size_t)BHZ * SSZ * 128];
__device__ __align__(16) bf    g_khc[(size_t)BHZ * SSZ * 384];  // (hi,hi,lo)
__device__ __align__(16) bf    g_qhc[(size_t)BHZ * SSZ * 384];
__device__ __align__(16) float g_gx[(size_t)BHZ * SSZ * 128];
__device__ __align__(16) float g_gy[(size_t)BHZ * SSZ * 128];
__device__ __align__(16) bf    g_kgc[(size_t)BHZ * SSZ * 384];  // gated k (hi,lo,hi)  [B side]
__device__ __align__(16) bf    g_qgc[(size_t)BHZ * SSZ * 384];  // gated q (hi,hi,lo)  [A side]
__device__ __align__(16) bf    g_vtc[(size_t)BHZ * 128 * 3072]; // v^T per head (hi,lo,hi)
__device__ __align__(16) bf    g_ctxc[(size_t)MT * 3072];       // ctx (hi,hi,lo)

// ---------------- helpers ----------------
__device__ __forceinline__ uint32_t smem_u32(const void* p) {
    uint32_t a;
    asm("{ .reg .u64 t; cvta.to.shared.u64 t, %1; cvt.u32.u64 %0, t; }" : "=r"(a) : "l"(p));
    return a;
}
__device__ __forceinline__ uint32_t sw128(uint32_t o) { return o ^ ((o >> 3) & 0x70); }
__device__ __forceinline__ void split_bf(float v, bf& hi, bf& lo) {
    hi = __float2bfloat16(v);
    lo = __float2bfloat16(v - __bfloat162float(hi));
}
// async-load one 128x64 bf16 tile (128B rows, SW128) into smem
__device__ __forceinline__ void cpa_tile(uint32_t sdst, const bf* src, long ld, int t) {
#pragma unroll
    for (int r = 0; r < 4; r++) {
        const int it = t + r * 256;
        const int row = it >> 3, seg = it & 7;
        const uint32_t d = sdst + sw128(row * 128 + seg * 16);
        const bf* p = src + (size_t)row * ld + seg * 8;
        asm volatile("cp.async.cg.shared.global [%0], [%1], 16;" :: "r"(d), "l"(p));
    }
}
#define CPA_COMMIT() asm volatile("cp.async.commit_group;" ::: "memory")
#define CPA_WAIT1()  asm volatile("cp.async.wait_group 1;" ::: "memory")
#define CPA_WAIT0()  asm volatile("cp.async.wait_group 0;" ::: "memory")

// one 64-wide-K chunk of 128x128 mma.sync work
#define MMA_CHUNK(sA, sB, ACC)                                                           \
    {                                                                                    \
        _Pragma("unroll")                                                                \
        for (int ks = 0; ks < 4; ks++) {                                                 \
            const int kb = ks * 32;                                                      \
            uint32_t a[4][4], bfr[4][2];                                                 \
            _Pragma("unroll")                                                            \
            for (int mi = 0; mi < 4; mi++) {                                             \
                const uint32_t addr = (sA) + sw128((warp_m * 64 + mi * 16 + (lane & 15)) * 128 \
                                                   + kb + (lane >> 4) * 16);             \
                asm volatile("ldmatrix.sync.aligned.m8n8.x4.shared.b16 {%0,%1,%2,%3}, [%4];" \
                    : "=r"(a[mi][0]), "=r"(a[mi][1]), "=r"(a[mi][2]), "=r"(a[mi][3]) : "r"(addr)); \
            }                                                                            \
            _Pragma("unroll")                                                            \
            for (int jp = 0; jp < 2; jp++) {                                             \
                const uint32_t addr = (sB) + sw128((warp_n * 32 + jp * 16 + ((lane >> 4) & 1) * 8 \
                                                    + (lane & 7)) * 128                  \
                                                   + kb + ((lane >> 3) & 1) * 16);       \
                asm volatile("ldmatrix.sync.aligned.m8n8.x4.shared.b16 {%0,%1,%2,%3}, [%4];" \
                    : "=r"(bfr[jp * 2][0]), "=r"(bfr[jp * 2][1]),                        \
                      "=r"(bfr[jp * 2 + 1][0]), "=r"(bfr[jp * 2 + 1][1]) : "r"(addr));   \
            }                                                                            \
            _Pragma("unroll")                                                            \
            for (int mi = 0; mi < 4; mi++)                                               \
                _Pragma("unroll")                                                        \
                for (int nj = 0; nj < 4; nj++)                                           \
                    asm volatile(                                                        \
                        "mma.sync.aligned.m16n8k16.row.col.f32.bf16.bf16.f32 "           \
                        "{%0,%1,%2,%3}, {%4,%5,%6,%7}, {%8,%9}, {%0,%1,%2,%3};"          \
                        : "+f"(ACC[mi][nj][0]), "+f"(ACC[mi][nj][1]),                    \
                          "+f"(ACC[mi][nj][2]), "+f"(ACC[mi][nj][3])                     \
                        : "r"(a[mi][0]), "r"(a[mi][1]), "r"(a[mi][2]), "r"(a[mi][3]),    \
                          "r"(bfr[nj][0]), "r"(bfr[nj][1]));                             \
        }                                                                                \
    }

// ---------------- mma.sync GEMM: C(128x128)=A[m][K']*B[n][K']^T ----------------
struct GArgs {
    const bf *A, *B;
    long lda, ldb, bsA, bsB;
    int K;
    const float* bias;
    float* of;
    bf* oc;
};

// MODE: 0=projV(transposed split) 1=projKQ(f32+split) 2=gate(f32) 5=final
template<int MODE>
__global__ __launch_bounds__(256) void tc_gemm(GArgs g)
{
    extern __shared__ __align__(16) char smt[];
    const uint32_t smbase = smem_u32(smt);
    const int t = threadIdx.x;
    const int lane = t & 31, wid = t >> 5;
    const int warp_m = wid >> 2, warp_n = wid & 3;

    const int m0 = blockIdx.x * 128;
    const int n0 = blockIdx.y * 128;
    const int bz = blockIdx.z;
    const bf* Ab = g.A + (size_t)bz * g.bsA + (size_t)m0 * g.lda;
    const bf* Bb = g.B + (size_t)bz * g.bsB + (size_t)n0 * g.ldb;

    float acc[4][4][4];
#pragma unroll
    for (int i = 0; i < 4; i++)
#pragma unroll
        for (int j = 0; j < 4; j++)
#pragma unroll
            for (int c = 0; c < 4; c++) acc[i][j][c] = 0.f;

    const int nch = g.K >> 6;

#define PREFETCH(i)                                                          \
    {                                                                        \
        cpa_tile(smbase + ((i) & 1) * 32768,         Ab + (i) * 64, g.lda, t); \
        cpa_tile(smbase + ((i) & 1) * 32768 + 16384, Bb + (i) * 64, g.ldb, t); \
    }

    PREFETCH(0);
    CPA_COMMIT();
    if (nch > 1) PREFETCH(1);
    CPA_COMMIT();

    for (int i = 0; i < nch; i++) {
        CPA_WAIT1();
        __syncthreads();
        const uint32_t sA = smbase + (i & 1) * 32768;
        const uint32_t sB = sA + 16384;
        MMA_CHUNK(sA, sB, acc);
        __syncthreads();
        if (i + 2 < nch) PREFETCH(i + 2);
        CPA_COMMIT();
    }
    CPA_WAIT0();
#undef PREFETCH

    // ---------------- epilogue: 4 col-blocks of 32 through smem staging ----------------
    float* stg = (float*)smt;   // 128 x 33 fp32
    for (int cb = 0; cb < 4; cb++) {
        __syncthreads();
        if (warp_n == cb) {
#pragma unroll
            for (int mi = 0; mi < 4; mi++)
#pragma unroll
                for (int nj = 0; nj < 4; nj++) {
                    const int r  = warp_m * 64 + mi * 16 + (lane >> 2);
                    const int cc = nj * 8 + (lane & 3) * 2;
                    stg[r * 33 + cc]           = acc[mi][nj][0];
                    stg[r * 33 + cc + 1]       = acc[mi][nj][1];
                    stg[(r + 8) * 33 + cc]     = acc[mi][nj][2];
                    stg[(r + 8) * 33 + cc + 1] = acc[mi][nj][3];
                }
        }
        __syncthreads();

        if (MODE == 0) {
            // v^T: per-head [bh][d][3S] (hi,lo,hi)
            const int dloc = t & 31, soff = (t >> 5) * 16;
            const int b = m0 >> 10, h = blockIdx.y, d = cb * 32 + dloc;
            const int scol = (m0 & 1023) + soff;
            bf hi16[16], lo16[16];
#pragma unroll
            for (int i2 = 0; i2 < 16; i2++) {
                float v = stg[(soff + i2) * 33 + dloc] + g.bias[n0 + d];
                split_bf(v, hi16[i2], lo16[i2]);
            }
            bf* dst = g.oc + ((size_t)(b * HSZ + h) * 128 + d) * 3072 + scol;
            uint4* hv = (uint4*)hi16; uint4* lv = (uint4*)lo16;
            *(uint4*)(dst) = hv[0];          *(uint4*)(dst + 8) = hv[1];
            *(uint4*)(dst + 1024) = lv[0];   *(uint4*)(dst + 1032) = lv[1];
            *(uint4*)(dst + 2048) = hv[0];   *(uint4*)(dst + 2056) = hv[1];
        } else {
            const int row = t >> 1, c0 = (t & 1) * 16;
            const float* sr = stg + row * 33 + c0;
            if (MODE == 1) {
                const int h = blockIdx.y, m = m0 + row, b = m >> 10, s = m & 1023;
                const int d0 = cb * 32 + c0;
                const size_t ri = (size_t)(b * HSZ + h) * SSZ + s;
                float* fd = g.of + ri * 128 + d0;
                bf* cd = g.oc + ri * 384 + d0;
#pragma unroll
                for (int c = 0; c < 16; c++) {
                    float v = sr[c] + g.bias[n0 + d0 + c];
                    fd[c] = v;
                    bf hi, lo; split_bf(v, hi, lo);
                    cd[c] = hi; cd[128 + c] = hi; cd[256 + c] = lo;
                }
            } else if (MODE == 2) {
                float* fd = g.of + (size_t)(m0 + row) * 128 + cb * 32 + c0;
#pragma unroll
                for (int c = 0; c < 16; c += 4) {
                    float4 w;
                    w.x = sr[c]     + g.bias[cb * 32 + c0 + c];
                    w.y = sr[c + 1] + g.bias[cb * 32 + c0 + c + 1];
                    w.z = sr[c + 2] + g.bias[cb * 32 + c0 + c + 2];
                    w.w = sr[c + 3] + g.bias[cb * 32 + c0 + c + 3];
                    *(float4*)(fd + c) = w;
                }
            } else {
                const int nt = n0 + cb * 32 + c0;
                float* fd = g.of + (size_t)(m0 + row) * 1024 + nt;
#pragma unroll
                for (int c = 0; c < 16; c += 4) {
                    float4 w;
                    w.x = sr[c]     + g.bias[nt + c];
                    w.y = sr[c + 1] + g.bias[nt + c + 1];
                    w.z = sr[c + 2] + g.bias[nt + c + 2];
                    w.w = sr[c + 3] + g.bias[nt + c + 3];
                    *(float4*)(fd + c) = w;
                }
            }
        }
    }
}

// ---------------- fused flash attention: scores+softmax+attV ----------------
// grid (8 q-tiles, 1, 64 bh), 256 threads. smem: 64KB buffers + stats.
#define FSM_PMAX 65536
#define FSM_PSUM (65536 + 2048)
#define FSM_MRUN (65536 + 4096)
#define FSM_LRUN (65536 + 4608)
#define FSM_MASK (65536 + 5120)
#define FSMEM    (65536 + 5376)

__global__ __launch_bounds__(256) void flash_att(
    const bf* __restrict__ qg, const bf* __restrict__ kg, const bf* __restrict__ vt,
    const unsigned char* __restrict__ mask, bf* __restrict__ ctx)
{
    extern __shared__ __align__(16) char smt[];
    const uint32_t smbase = smem_u32(smt);
    float* pmax = (float*)(smt + FSM_PMAX);     // [4][128]
    float* psum = (float*)(smt + FSM_PSUM);     // [4][128]
    float* m_run = (float*)(smt + FSM_MRUN);    // [128]
    float* l_run = (float*)(smt + FSM_LRUN);    // [128]
    unsigned char* mk = (unsigned char*)(smt + FSM_MASK);

    const int t = threadIdx.x, lane = t & 31, wid = t >> 5;
    const int warp_m = wid >> 2, warp_n = wid & 3;
    const int m0 = blockIdx.x * 128;
    const int bh = blockIdx.z, b = bh >> 3, h = bh & 7;

    const bf* Aq = qg + (size_t)bh * SSZ * 384 + (size_t)m0 * 384;
    const bf* Bk = kg + (size_t)bh * SSZ * 384;
    const bf* Vt = vt + (size_t)bh * 128 * 3072;

    float oacc[4][4][4];
#pragma unroll
    for (int i = 0; i < 4; i++)
#pragma unroll
        for (int j = 0; j < 4; j++)
#pragma unroll
            for (int c = 0; c < 4; c++) oacc[i][j][c] = 0.f;

    if (t < 128) { m_run[t] = -1e30f; l_run[t] = 0.f; }
    __syncthreads();

    for (int kt = 0; kt < 8; kt++) {
        if (t < 128) mk[t] = mask[b * SSZ + kt * 128 + t];
        const bf* Bb = Bk + (size_t)(kt * 128) * 384;

        float sacc[4][4][4];
#pragma unroll
        for (int i = 0; i < 4; i++)
#pragma unroll
            for (int j = 0; j < 4; j++)
#pragma unroll
                for (int c = 0; c < 4; c++) sacc[i][j][c] = 0.f;

        // ---- S phase: 6 chunks of 64 over K'=384 ----
#define SPRE(i)                                                              \
        {                                                                    \
            cpa_tile(smbase + ((i) & 1) * 32768,         Aq + (i) * 64, 384, t); \
            cpa_tile(smbase + ((i) & 1) * 32768 + 16384, Bb + (i) * 64, 384, t); \
        }
        SPRE(0); CPA_COMMIT();
        SPRE(1); CPA_COMMIT();
        for (int i = 0; i < 6; i++) {
            CPA_WAIT1();
            __syncthreads();
            const uint32_t sA = smbase + (i & 1) * 32768;
            const uint32_t sB = sA + 16384;
            MMA_CHUNK(sA, sB, sacc);
            __syncthreads();
            if (i + 2 < 6) SPRE(i + 2);
            CPA_COMMIT();
        }
        CPA_WAIT0();
#undef SPRE

        // ---- scale + mask ----
        const float scl = 0.08838834764831845f;
#pragma unroll
        for (int mi = 0; mi < 4; mi++)
#pragma unroll
            for (int nj = 0; nj < 4; nj++) {
                const int cbase = warp_n * 32 + nj * 8 + (lane & 3) * 2;
                const bool mk0 = mk[cbase] != 0, mk1 = mk[cbase + 1] != 0;
                sacc[mi][nj][0] = mk0 ? -1e9f : sacc[mi][nj][0] * scl;
                sacc[mi][nj][1] = mk1 ? -1e9f : sacc[mi][nj][1] * scl;
                sacc[mi][nj][2] = mk0 ? -1e9f : sacc[mi][nj][2] * scl;
                sacc[mi][nj][3] = mk1 ? -1e9f : sacc[mi][nj][3] * scl;
            }

        // ---- per-warp row-max partials ----
#pragma unroll
        for (int mi = 0; mi < 4; mi++) {
            float mx0 = -1e30f, mx1 = -1e30f;
#pragma unroll
            for (int nj = 0; nj < 4; nj++) {
                mx0 = fmaxf(mx0, fmaxf(sacc[mi][nj][0], sacc[mi][nj][1]));
                mx1 = fmaxf(mx1, fmaxf(sacc[mi][nj][2], sacc[mi][nj][3]));
            }
            mx0 = fmaxf(mx0, __shfl_xor_sync(0xFFFFFFFFu, mx0, 1));
            mx0 = fmaxf(mx0, __shfl_xor_sync(0xFFFFFFFFu, mx0, 2));
            mx1 = fmaxf(mx1, __shfl_xor_sync(0xFFFFFFFFu, mx1, 1));
            mx1 = fmaxf(mx1, __shfl_xor_sync(0xFFFFFFFFu, mx1, 2));
            if ((lane & 3) == 0) {
                const int r = warp_m * 64 + mi * 16 + (lane >> 2);
                pmax[warp_n * 128 + r] = mx0;
                pmax[warp_n * 128 + r + 8] = mx1;
            }
        }
        __syncthreads();

        // ---- P = exp(S - m_new), rescale O, partial row sums ----
#pragma unroll
        for (int mi = 0; mi < 4; mi++) {
            const int r0 = warp_m * 64 + mi * 16 + (lane >> 2), r1 = r0 + 8;
            const float mo0 = m_run[r0], mo1 = m_run[r1];
            float mn0 = fmaxf(fmaxf(pmax[r0], pmax[128 + r0]), fmaxf(pmax[256 + r0], pmax[384 + r0]));
            float mn1 = fmaxf(fmaxf(pmax[r1], pmax[128 + r1]), fmaxf(pmax[256 + r1], pmax[384 + r1]));
            mn0 = fmaxf(mn0, mo0); mn1 = fmaxf(mn1, mo1);
            const float f0 = __expf(mo0 - mn0), f1 = __expf(mo1 - mn1);
            float s0 = 0.f, s1 = 0.f;
#pragma unroll
            for (int nj = 0; nj < 4; nj++) {
                sacc[mi][nj][0] = __expf(sacc[mi][nj][0] - mn0); s0 += sacc[mi][nj][0];
                sacc[mi][nj][1] = __expf(sacc[mi][nj][1] - mn0); s0 += sacc[mi][nj][1];
                sacc[mi][nj][2] = __expf(sacc[mi][nj][2] - mn1); s1 += sacc[mi][nj][2];
                sacc[mi][nj][3] = __expf(sacc[mi][nj][3] - mn1); s1 += sacc[mi][nj][3];
                oacc[mi][nj][0] *= f0; oacc[mi][nj][1] *= f0;
                oacc[mi][nj][2] *= f1; oacc[mi][nj][3] *= f1;
            }
            s0 += __shfl_xor_sync(0xFFFFFFFFu, s0, 1); s0 += __shfl_xor_sync(0xFFFFFFFFu, s0, 2);
            s1 += __shfl_xor_sync(0xFFFFFFFFu, s1, 1); s1 += __shfl_xor_sync(0xFFFFFFFFu, s1, 2);
            if ((lane & 3) == 0) {
                psum[warp_n * 128 + r0] = s0;
                psum[warp_n * 128 + r1] = s1;
            }
        }
        __syncthreads();
        if (t < 128) {
            const float mo = m_run[t];
            float mn = fmaxf(fmaxf(pmax[t], pmax[128 + t]), fmaxf(pmax[256 + t], pmax[384 + t]));
            mn = fmaxf(mn, mo);
            l_run[t] = l_run[t] * __expf(mo - mn)
                     + psum[t] + psum[128 + t] + psum[256 + t] + psum[384 + t];
            m_run[t] = mn;
        }

        // ---- P·V phase: 6 chunks; P bufs @ 0/16K, V bufs @ 32K/48K ----
        // chunk c: P = (c<4 ? hi : lo), V term = {0,0,1,1,2,2}[c], half h=c&1
        cpa_tile(smbase + 32768, Vt + (size_t)kt * 128, 3072, t);
        CPA_COMMIT();
        cpa_tile(smbase + 49152, Vt + (size_t)kt * 128 + 64, 3072, t);
        CPA_COMMIT();
        for (int c = 0; c < 6; c++) {
            CPA_WAIT1();
            __syncthreads();
            // write P chunk into Pbuf[c&1] (warps owning these 64 s-cols)
            if ((warp_n >> 1) == (c & 1)) {
                const bool lo = (c >= 4);
                char* pb = smt + (c & 1) * 16384;
#pragma unroll
                for (int mi = 0; mi < 4; mi++)
#pragma unroll
                    for (int nj = 0; nj < 4; nj++) {
                        const int r0 = warp_m * 64 + mi * 16 + (lane >> 2);
                        const int lc = (warp_n & 1) * 32 + nj * 8 + (lane & 3) * 2;
                        __nv_bfloat162 w0, w1;
                        if (!lo) {
                            w0.x = __float2bfloat16(sacc[mi][nj][0]);
                            w0.y = __float2bfloat16(sacc[mi][nj][1]);
                            w1.x = __float2bfloat16(sacc[mi][nj][2]);
                            w1.y = __float2bfloat16(sacc[mi][nj][3]);
                        } else {
                            bf hh, ll;
                            split_bf(sacc[mi][nj][0], hh, ll); w0.x = ll;
                            split_bf(sacc[mi][nj][1], hh, ll); w0.y = ll;
                            split_bf(sacc[mi][nj][2], hh, ll); w1.x = ll;
                            split_bf(sacc[mi][nj][3], hh, ll); w1.y = ll;
                        }
                        *(__nv_bfloat162*)(pb + sw128(r0 * 128 + lc * 2)) = w0;
                        *(__nv_bfloat162*)(pb + sw128((r0 + 8) * 128 + lc * 2)) = w1;
                    }
            }
            __syncthreads();
            const uint32_t sA = smbase + (c & 1) * 16384;
            const uint32_t sB = smbase + 32768 + (c & 1) * 16384;
            MMA_CHUNK(sA, sB, oacc);
            __syncthreads();
            if (c + 2 < 6) {
                const int cn = c + 2;
                const int vterm = cn >> 1;
                cpa_tile(smbase + 32768 + (cn & 1) * 16384,
                         Vt + (size_t)vterm * 1024 + (size_t)kt * 128 + (cn & 1) * 64, 3072, t);
            }
            CPA_COMMIT();
        }
        CPA_WAIT0();
        __syncthreads();   // all mma done before next kt overwrites buffers
    }

    // ---- epilogue: O / l, split-store to ctx (hi|hi|lo) ----
    float inv0[4], inv1[4];
#pragma unroll
    for (int mi = 0; mi < 4; mi++) {
        const int r0 = warp_m * 64 + mi * 16 + (lane >> 2);
        inv0[mi] = 1.f / l_run[r0];
        inv1[mi] = 1.f / l_run[r0 + 8];
    }
    float* stg = (float*)smt;
    for (int cb = 0; cb < 4; cb++) {
        __syncthreads();
        if (warp_n == cb) {
#pragma unroll
            for (int mi = 0; mi < 4; mi++)
#pragma unroll
                for (int nj = 0; nj < 4; nj++) {
                    const int r  = warp_m * 64 + mi * 16 + (lane >> 2);
                    const int cc = nj * 8 + (lane & 3) * 2;
                    stg[r * 33 + cc]           = oacc[mi][nj][0] * inv0[mi];
                    stg[r * 33 + cc + 1]       = oacc[mi][nj][1] * inv0[mi];
                    stg[(r + 8) * 33 + cc]     = oacc[mi][nj][2] * inv1[mi];
                    stg[(r + 8) * 33 + cc + 1] = oacc[mi][nj][3] * inv1[mi];
                }
        }
        __syncthreads();
        const int row = t >> 1, c0 = (t & 1) * 16;
        const float* sr = stg + row * 33 + c0;
        const int n = cb * 32 + c0;
        bf* cd = ctx + ((size_t)b * SSZ + m0 + row) * 3072 + h * 128 + n;
        bf hi16[16], lo16[16];
#pragma unroll
        for (int c = 0; c < 16; c++) split_bf(sr[c], hi16[c], lo16[c]);
        uint4* hv = (uint4*)hi16; uint4* lv = (uint4*)lo16;
        *(uint4*)(cd) = hv[0];          *(uint4*)(cd + 8) = hv[1];
        *(uint4*)(cd + 1024) = hv[0];   *(uint4*)(cd + 1032) = hv[1];
        *(uint4*)(cd + 2048) = lv[0];   *(uint4*)(cd + 2056) = lv[1];
    }
}

// ---------------- prep kernels ----------------
__global__ __launch_bounds__(256) void split_act(const float* v, const float* k, const float* q)
{
    const float* s = blockIdx.z == 0 ? v : blockIdx.z == 1 ? k : q;
    bf* dst = g_xc[blockIdx.z];
    const size_t i = ((size_t)blockIdx.x * 256 + threadIdx.x) * 4;
    const size_t row = i >> 10, col = i & 1023;
    float4 x = *(const float4*)(s + i);
    bf h[4], l[4];
    split_bf(x.x, h[0], l[0]); split_bf(x.y, h[1], l[1]);
    split_bf(x.z, h[2], l[2]); split_bf(x.w, h[3], l[3]);
    bf* d = dst + row * 3072 + col;
    *(uint2*)(d) = *(uint2*)h;
    *(uint2*)(d + 1024) = *(uint2*)h;
    *(uint2*)(d + 2048) = *(uint2*)l;
}

__global__ void wsplit(const float* W, bf* Wc, int K, int N)
{
    __shared__ float sm[32][33];
    const int k0 = blockIdx.y * 32, n0 = blockIdx.x * 32;
    for (int r = threadIdx.y; r < 32; r += 8)
        sm[r][threadIdx.x] = W[(size_t)(k0 + r) * N + n0 + threadIdx.x];
    __syncthreads();
    for (int r = threadIdx.y; r < 32; r += 8) {
        bf hi, lo; split_bf(sm[threadIdx.x][r], hi, lo);
        bf* d = Wc + (size_t)(n0 + r) * 3 * K + k0 + threadIdx.x;
        d[0] = hi; d[K] = lo; d[2 * K] = hi;
    }
}

__global__ __launch_bounds__(128) void gate_apply(const float* Wg2, const float* bg2)
{
    const size_t row = blockIdx.x;
    const int d = threadIdx.x;
    const size_t o = row * 128 + d;
    float tv = g_gx[o] * g_gy[o];
    float s0 = tv * Wg2[d * 2], s1 = tv * Wg2[d * 2 + 1];
    const int lane = d & 31, w = d >> 5;
#pragma unroll
    for (int off = 16; off; off >>= 1) {
        s0 += __shfl_xor_sync(0xFFFFFFFFu, s0, off);
        s1 += __shfl_xor_sync(0xFFFFFFFFu, s1, off);
    }
    __shared__ float r0[4], r1[4];
    if (lane == 0) { r0[w] = s0; r1[w] = s1; }
    __syncthreads();
    float t0 = r0[0] + r0[1] + r0[2] + r0[3];
    float t1 = r1[0] + r1[1] + r1[2] + r1[3];
    float gk = 1.f / (1.f + __expf(-(t0 + bg2[0])));
    float gq = 1.f / (1.f + __expf(-(t1 + bg2[1])));
    bf hi, lo;
    split_bf(g_kh[o] * gk, hi, lo);
    bf* kd = g_kgc + row * 384 + d;                       // (hi,lo,hi)
    kd[0] = hi; kd[128] = lo; kd[256] = hi;
    split_bf(g_qh[o] * gq, hi, lo);
    bf* qd = g_qgc + row * 384 + d;                       // (hi,hi,lo)
    qd[0] = hi; qd[128] = hi; qd[256] = lo;
}

// ---------------- launch ----------------
#define TCSMEM 65536

extern "C" void kernel_launch(void* const* d_in, const int* in_sizes, int n_in,
                              void* d_out, int out_size)
{
    (void)in_sizes; (void)n_in; (void)out_size;
    const float* v  = (const float*)d_in[0];
    const float* k  = (const float*)d_in[1];
    const float* q  = (const float*)d_in[2];
    const unsigned char* mask = (const unsigned char*)d_in[3];
    const float* Wv = (const float*)d_in[4];  const float* bv = (const float*)d_in[5];
    const float* Wk = (const float*)d_in[6];  const float* bk = (const float*)d_in[7];
    const float* Wq = (const float*)d_in[8];  const float* bq = (const float*)d_in[9];
    const float* Wm = (const float*)d_in[10]; const float* bm = (const float*)d_in[11];
    const float* WgX = (const float*)d_in[12]; const float* bgX = (const float*)d_in[13];
    const float* WgY = (const float*)d_in[14]; const float* bgY = (const float*)d_in[15];
    const float* Wg2 = (const float*)d_in[16]; const float* bg2 = (const float*)d_in[17];
    float* outp = (float*)d_out;

    cudaFuncSetAttribute(tc_gemm<0>, cudaFuncAttributeMaxDynamicSharedMemorySize, TCSMEM);
    cudaFuncSetAttribute(tc_gemm<1>, cudaFuncAttributeMaxDynamicSharedMemorySize, TCSMEM);
    cudaFuncSetAttribute(tc_gemm<2>, cudaFuncAttributeMaxDynamicSharedMemorySize, TCSMEM);
    cudaFuncSetAttribute(tc_gemm<5>, cudaFuncAttributeMaxDynamicSharedMemorySize, TCSMEM);
    cudaFuncSetAttribute(flash_att,  cudaFuncAttributeMaxDynamicSharedMemorySize, FSMEM);

    bf* wc0; bf* wc1; bf* wc2; bf* wc3; bf* wg0; bf* wg1;
    bf* xc0; bf* xc1; bf* xc2;
    cudaGetSymbolAddress((void**)&wc0, g_wc);  wc1 = wc0 + (size_t)1024 * 3072;
    wc2 = wc1 + (size_t)1024 * 3072; wc3 = wc2 + (size_t)1024 * 3072;
    cudaGetSymbolAddress((void**)&wg0, g_wgc); wg1 = wg0 + (size_t)128 * 384;
    cudaGetSymbolAddress((void**)&xc0, g_xc);  xc1 = xc0 + (size_t)MT * 3072; xc2 = xc1 + (size_t)MT * 3072;
    float *kh, *qh, *gx, *gy;
    bf *khc, *qhc, *kgc, *qgc, *vtc, *ctxc;
    cudaGetSymbolAddress((void**)&kh, g_kh);   cudaGetSymbolAddress((void**)&qh, g_qh);
    cudaGetSymbolAddress((void**)&gx, g_gx);   cudaGetSymbolAddress((void**)&gy, g_gy);
    cudaGetSymbolAddress((void**)&khc, g_khc); cudaGetSymbolAddress((void**)&qhc, g_qhc);
    cudaGetSymbolAddress((void**)&kgc, g_kgc); cudaGetSymbolAddress((void**)&qgc, g_qgc);
    cudaGetSymbolAddress((void**)&vtc, g_vtc); cudaGetSymbolAddress((void**)&ctxc, g_ctxc);

    split_act<<<dim3(8192, 1, 3), 256>>>(v, k, q);
    wsplit<<<dim3(32, 32), dim3(32, 8)>>>(Wv, wc0, 1024, 1024);
    wsplit<<<dim3(32, 32), dim3(32, 8)>>>(Wk, wc1, 1024, 1024);
    wsplit<<<dim3(32, 32), dim3(32, 8)>>>(Wq, wc2, 1024, 1024);
    wsplit<<<dim3(32, 32), dim3(32, 8)>>>(Wm, wc3, 1024, 1024);
    wsplit<<<dim3(4, 4),   dim3(32, 8)>>>(WgX, wg0, 128, 128);
    wsplit<<<dim3(4, 4),   dim3(32, 8)>>>(WgY, wg1, 128, 128);

    GArgs a = {};
    // proj V -> vtc
    a.A = xc0; a.B = wc0; a.lda = 3072; a.ldb = 3072; a.bsA = 0; a.bsB = 0;
    a.K = 3072; a.bias = bv; a.oc = vtc;
    tc_gemm<0><<<dim3(64, 8, 1), 256, TCSMEM>>>(a);
    // proj K -> kh + khc
    a.B = wc1; a.bias = bk; a.of = kh; a.oc = khc; a.A = xc1;
    tc_gemm<1><<<dim3(64, 8, 1), 256, TCSMEM>>>(a);
    // proj Q -> qh + qhc
    a.B = wc2; a.bias = bq; a.of = qh; a.oc = qhc; a.A = xc2;
    tc_gemm<1><<<dim3(64, 8, 1), 256, TCSMEM>>>(a);
    // gate X / Y
    a.A = khc; a.B = wg0; a.lda = 384; a.ldb = 384; a.K = 384; a.bias = bgX; a.of = gx; a.oc = nullptr;
    tc_gemm<2><<<dim3(512, 1, 1), 256, TCSMEM>>>(a);
    a.A = qhc; a.B = wg1; a.bias = bgY; a.of = gy;
    tc_gemm<2><<<dim3(512, 1, 1), 256, TCSMEM>>>(a);

    gate_apply<<<BHZ * SSZ, 128>>>(Wg2, bg2);

    // fused scores+softmax+attV
    flash_att<<<dim3(8, 1, BHZ), 256, FSMEM>>>(qgc, kgc, vtc, mask, ctxc);

    // final
    a.A = ctxc; a.B = wc3; a.lda = 3072; a.ldb = 3072; a.bsA = 0; a.bsB = 0;
    a.K = 3072; a.bias = bm; a.of = outp; a.oc = nullptr;
    tc_gemm<5><<<dim3(64, 8, 1), 256, TCSMEM>>>(a);
}

// round 9
// speedup vs baseline: 1.1322x; 1.0610x over previous
#include <cuda_runtime.h>
#include <cuda_bf16.h>
#include <cstdint>
#include <math.h>

#define SSZ 1024
#define HSZ 8
#define BHZ 64
#define MT  8192
typedef __nv_bfloat16 bf;

// ---------------- scratch (device globals) ----------------
__device__ __align__(16) bf    g_xc[3][(size_t)MT * 3072];      // split acts (hi,hi,lo)
__device__ __align__(16) bf    g_wc[4][(size_t)1024 * 3072];    // W^T split (hi,lo,hi): v,k,q,m
__device__ __align__(16) bf    g_wgc[2][(size_t)128 * 384];     // WgX^T, WgY^T split (hi,lo,hi)
__device__ __align__(16) float g_kh[(size_t)BHZ * SSZ * 128];
__device__ __align__(16) float g_qh[(size_t)BHZ * SSZ * 128];
__device__ __align__(16) bf    g_khc[(size_t)BHZ * SSZ * 384];  // (hi,hi,lo)
__device__ __align__(16) bf    g_qhc[(size_t)BHZ * SSZ * 384];
__device__ __align__(16) float g_gx[(size_t)BHZ * SSZ * 128];
__device__ __align__(16) float g_gy[(size_t)BHZ * SSZ * 128];
__device__ __align__(16) bf    g_kgc[(size_t)BHZ * SSZ * 384];  // gated k (hi,lo,hi)  [B side]
__device__ __align__(16) bf    g_qgc[(size_t)BHZ * SSZ * 384];  // gated q (hi,hi,lo)  [A side]
__device__ __align__(16) bf    g_vtc[(size_t)BHZ * 128 * 3072]; // v^T per head (hi,lo,hi)
__device__ __align__(16) bf    g_ctxc[(size_t)MT * 3072];       // ctx (hi,hi,lo)

// ---------------- helpers ----------------
__device__ __forceinline__ uint32_t smem_u32(const void* p) {
    uint32_t a;
    asm("{ .reg .u64 t; cvta.to.shared.u64 t, %1; cvt.u32.u64 %0, t; }" : "=r"(a) : "l"(p));
    return a;
}
__device__ __forceinline__ uint32_t sw128(uint32_t o) { return o ^ ((o >> 3) & 0x70); }
__device__ __forceinline__ void split_bf(float v, bf& hi, bf& lo) {
    hi = __float2bfloat16(v);
    lo = __float2bfloat16(v - __bfloat162float(hi));
}
// async-load one 128x64 bf16 tile (128B rows, SW128) into smem
__device__ __forceinline__ void cpa_tile(uint32_t sdst, const bf* src, long ld, int t) {
#pragma unroll
    for (int r = 0; r < 4; r++) {
        const int it = t + r * 256;
        const int row = it >> 3, seg = it & 7;
        const uint32_t d = sdst + sw128(row * 128 + seg * 16);
        const bf* p = src + (size_t)row * ld + seg * 8;
        asm volatile("cp.async.cg.shared.global [%0], [%1], 16;" :: "r"(d), "l"(p));
    }
}
#define CPA_COMMIT() asm volatile("cp.async.commit_group;" ::: "memory")
#define CPA_WAIT2()  asm volatile("cp.async.wait_group 2;" ::: "memory")
#define CPA_WAIT1()  asm volatile("cp.async.wait_group 1;" ::: "memory")
#define CPA_WAIT0()  asm volatile("cp.async.wait_group 0;" ::: "memory")

// one 64-wide-K chunk of 128x128 mma.sync work
#define MMA_CHUNK(sA, sB, ACC)                                                           \
    {                                                                                    \
        _Pragma("unroll")                                                                \
        for (int ks = 0; ks < 4; ks++) {                                                 \
            const int kb = ks * 32;                                                      \
            uint32_t a[4][4], bfr[4][2];                                                 \
            _Pragma("unroll")                                                            \
            for (int mi = 0; mi < 4; mi++) {                                             \
                const uint32_t addr = (sA) + sw128((warp_m * 64 + mi * 16 + (lane & 15)) * 128 \
                                                   + kb + (lane >> 4) * 16);             \
                asm volatile("ldmatrix.sync.aligned.m8n8.x4.shared.b16 {%0,%1,%2,%3}, [%4];" \
                    : "=r"(a[mi][0]), "=r"(a[mi][1]), "=r"(a[mi][2]), "=r"(a[mi][3]) : "r"(addr)); \
            }                                                                            \
            _Pragma("unroll")                                                            \
            for (int jp = 0; jp < 2; jp++) {                                             \
                const uint32_t addr = (sB) + sw128((warp_n * 32 + jp * 16 + ((lane >> 4) & 1) * 8 \
                                                    + (lane & 7)) * 128                  \
                                                   + kb + ((lane >> 3) & 1) * 16);       \
                asm volatile("ldmatrix.sync.aligned.m8n8.x4.shared.b16 {%0,%1,%2,%3}, [%4];" \
                    : "=r"(bfr[jp * 2][0]), "=r"(bfr[jp * 2][1]),                        \
                      "=r"(bfr[jp * 2 + 1][0]), "=r"(bfr[jp * 2 + 1][1]) : "r"(addr));   \
            }                                                                            \
            _Pragma("unroll")                                                            \
            for (int mi = 0; mi < 4; mi++)                                               \
                _Pragma("unroll")                                                        \
                for (int nj = 0; nj < 4; nj++)                                           \
                    asm volatile(                                                        \
                        "mma.sync.aligned.m16n8k16.row.col.f32.bf16.bf16.f32 "           \
                        "{%0,%1,%2,%3}, {%4,%5,%6,%7}, {%8,%9}, {%0,%1,%2,%3};"          \
                        : "+f"(ACC[mi][nj][0]), "+f"(ACC[mi][nj][1]),                    \
                          "+f"(ACC[mi][nj][2]), "+f"(ACC[mi][nj][3])                     \
                        : "r"(a[mi][0]), "r"(a[mi][1]), "r"(a[mi][2]), "r"(a[mi][3]),    \
                          "r"(bfr[nj][0]), "r"(bfr[nj][1]));                             \
        }                                                                                \
    }

// ---------------- mma.sync GEMM: C(128x128)=A[m][K']*B[n][K']^T ----------------
struct GArgs {
    const bf *A, *B;
    long lda, ldb, bsA, bsB;
    int K;
    const float* bias;
    float* of;
    bf* oc;
};

// MODE: 0=projV(transposed split) 1=projKQ(f32+split) 2=gate(f32) 5=final
template<int MODE>
__global__ __launch_bounds__(256) void tc_gemm(GArgs g)
{
    extern __shared__ __align__(16) char smt[];
    const uint32_t smbase = smem_u32(smt);
    const int t = threadIdx.x;
    const int lane = t & 31, wid = t >> 5;
    const int warp_m = wid >> 2, warp_n = wid & 3;

    const int m0 = blockIdx.x * 128;
    const int n0 = blockIdx.y * 128;
    const int bz = blockIdx.z;
    const bf* Ab = g.A + (size_t)bz * g.bsA + (size_t)m0 * g.lda;
    const bf* Bb = g.B + (size_t)bz * g.bsB + (size_t)n0 * g.ldb;

    float acc[4][4][4];
#pragma unroll
    for (int i = 0; i < 4; i++)
#pragma unroll
        for (int j = 0; j < 4; j++)
#pragma unroll
            for (int c = 0; c < 4; c++) acc[i][j][c] = 0.f;

    const int nch = g.K >> 6;

#define PREFETCH(i)                                                          \
    {                                                                        \
        cpa_tile(smbase + ((i) & 1) * 32768,         Ab + (i) * 64, g.lda, t); \
        cpa_tile(smbase + ((i) & 1) * 32768 + 16384, Bb + (i) * 64, g.ldb, t); \
    }

    PREFETCH(0);
    CPA_COMMIT();
    if (nch > 1) PREFETCH(1);
    CPA_COMMIT();

    for (int i = 0; i < nch; i++) {
        CPA_WAIT1();
        __syncthreads();
        const uint32_t sA = smbase + (i & 1) * 32768;
        const uint32_t sB = sA + 16384;
        MMA_CHUNK(sA, sB, acc);
        __syncthreads();
        if (i + 2 < nch) PREFETCH(i + 2);
        CPA_COMMIT();
    }
    CPA_WAIT0();
#undef PREFETCH

    // ---------------- epilogue: 4 col-blocks of 32 through smem staging ----------------
    float* stg = (float*)smt;   // 128 x 33 fp32
    for (int cb = 0; cb < 4; cb++) {
        __syncthreads();
        if (warp_n == cb) {
#pragma unroll
            for (int mi = 0; mi < 4; mi++)
#pragma unroll
                for (int nj = 0; nj < 4; nj++) {
                    const int r  = warp_m * 64 + mi * 16 + (lane >> 2);
                    const int cc = nj * 8 + (lane & 3) * 2;
                    stg[r * 33 + cc]           = acc[mi][nj][0];
                    stg[r * 33 + cc + 1]       = acc[mi][nj][1];
                    stg[(r + 8) * 33 + cc]     = acc[mi][nj][2];
                    stg[(r + 8) * 33 + cc + 1] = acc[mi][nj][3];
                }
        }
        __syncthreads();

        if (MODE == 0) {
            // v^T: per-head [bh][d][3S] (hi,lo,hi)
            const int dloc = t & 31, soff = (t >> 5) * 16;
            const int b = m0 >> 10, h = blockIdx.y, d = cb * 32 + dloc;
            const int scol = (m0 & 1023) + soff;
            bf hi16[16], lo16[16];
#pragma unroll
            for (int i2 = 0; i2 < 16; i2++) {
                float v = stg[(soff + i2) * 33 + dloc] + g.bias[n0 + d];
                split_bf(v, hi16[i2], lo16[i2]);
            }
            bf* dst = g.oc + ((size_t)(b * HSZ + h) * 128 + d) * 3072 + scol;
            uint4* hv = (uint4*)hi16; uint4* lv = (uint4*)lo16;
            *(uint4*)(dst) = hv[0];          *(uint4*)(dst + 8) = hv[1];
            *(uint4*)(dst + 1024) = lv[0];   *(uint4*)(dst + 1032) = lv[1];
            *(uint4*)(dst + 2048) = hv[0];   *(uint4*)(dst + 2056) = hv[1];
        } else {
            const int row = t >> 1, c0 = (t & 1) * 16;
            const float* sr = stg + row * 33 + c0;
            if (MODE == 1) {
                const int h = blockIdx.y, m = m0 + row, b = m >> 10, s = m & 1023;
                const int d0 = cb * 32 + c0;
                const size_t ri = (size_t)(b * HSZ + h) * SSZ + s;
                float* fd = g.of + ri * 128 + d0;
                bf* cd = g.oc + ri * 384 + d0;
#pragma unroll
                for (int c = 0; c < 16; c++) {
                    float v = sr[c] + g.bias[n0 + d0 + c];
                    fd[c] = v;
                    bf hi, lo; split_bf(v, hi, lo);
                    cd[c] = hi; cd[128 + c] = hi; cd[256 + c] = lo;
                }
            } else if (MODE == 2) {
                float* fd = g.of + (size_t)(m0 + row) * 128 + cb * 32 + c0;
#pragma unroll
                for (int c = 0; c < 16; c += 4) {
                    float4 w;
                    w.x = sr[c]     + g.bias[cb * 32 + c0 + c];
                    w.y = sr[c + 1] + g.bias[cb * 32 + c0 + c + 1];
                    w.z = sr[c + 2] + g.bias[cb * 32 + c0 + c + 2];
                    w.w = sr[c + 3] + g.bias[cb * 32 + c0 + c + 3];
                    *(float4*)(fd + c) = w;
                }
            } else {
                const int nt = n0 + cb * 32 + c0;
                float* fd = g.of + (size_t)(m0 + row) * 1024 + nt;
#pragma unroll
                for (int c = 0; c < 16; c += 4) {
                    float4 w;
                    w.x = sr[c]     + g.bias[nt + c];
                    w.y = sr[c + 1] + g.bias[nt + c + 1];
                    w.z = sr[c + 2] + g.bias[nt + c + 2];
                    w.w = sr[c + 3] + g.bias[nt + c + 3];
                    *(float4*)(fd + c) = w;
                }
            }
        }
    }
}

// ---------------- fused flash attention v2 ----------------
// 1 CTA/SM (reg-bound) -> spend smem freely:
//   QB: Q resident, 6 tiles (96KB)   PB: P hi/lo, 4 tiles (64KB)
//   SB: 3-buffer stream ring for K then V (48KB)   stats (~5KB)
#define FQB  0
#define FPB  98304
#define FSB  163840
#define FSM_PMAX 212992
#define FSM_PSUM (212992 + 2048)
#define FSM_MRUN (212992 + 4096)
#define FSM_LRUN (212992 + 4608)
#define FSM_MASK (212992 + 5120)
#define FSMEM    (212992 + 5376)

__global__ __launch_bounds__(256) void flash_att(
    const bf* __restrict__ qg, const bf* __restrict__ kg, const bf* __restrict__ vt,
    const unsigned char* __restrict__ mask, bf* __restrict__ ctx)
{
    extern __shared__ __align__(16) char smt[];
    const uint32_t smbase = smem_u32(smt);
    float* pmax = (float*)(smt + FSM_PMAX);     // [4][128]
    float* psum = (float*)(smt + FSM_PSUM);     // [4][128]
    float* m_run = (float*)(smt + FSM_MRUN);    // [128]
    float* l_run = (float*)(smt + FSM_LRUN);    // [128]
    unsigned char* mk = (unsigned char*)(smt + FSM_MASK);

    const int t = threadIdx.x, lane = t & 31, wid = t >> 5;
    const int warp_m = wid >> 2, warp_n = wid & 3;
    const int m0 = blockIdx.x * 128;
    const int bh = blockIdx.z, b = bh >> 3, h = bh & 7;

    const bf* Aq = qg + (size_t)bh * SSZ * 384 + (size_t)m0 * 384;
    const bf* Bk = kg + (size_t)bh * SSZ * 384;
    const bf* Vt = vt + (size_t)bh * 128 * 3072;

    // load Q resident (once)
#pragma unroll
    for (int c = 0; c < 6; c++)
        cpa_tile(smbase + FQB + c * 16384, Aq + c * 64, 384, t);
    CPA_COMMIT();

    float oacc[4][4][4];
#pragma unroll
    for (int i = 0; i < 4; i++)
#pragma unroll
        for (int j = 0; j < 4; j++)
#pragma unroll
            for (int c = 0; c < 4; c++) oacc[i][j][c] = 0.f;

    if (t < 128) { m_run[t] = -1e30f; l_run[t] = 0.f; }
    CPA_WAIT0();
    __syncthreads();

    for (int kt = 0; kt < 8; kt++) {
        if (t < 128) mk[t] = mask[b * SSZ + kt * 128 + t];
        const bf* Bb = Bk + (size_t)(kt * 128) * 384;

        float sacc[4][4][4];
#pragma unroll
        for (int i = 0; i < 4; i++)
#pragma unroll
            for (int j = 0; j < 4; j++)
#pragma unroll
                for (int c = 0; c < 4; c++) sacc[i][j][c] = 0.f;

        // ---- S phase: K streams through 3-buf ring vs resident Q ----
        cpa_tile(smbase + FSB, Bb, 384, t); CPA_COMMIT();
        cpa_tile(smbase + FSB + 16384, Bb + 64, 384, t); CPA_COMMIT();
#pragma unroll 3
        for (int c = 0; c < 6; c++) {
            CPA_WAIT1();
            __syncthreads();
            if (c + 2 < 6)
                cpa_tile(smbase + FSB + ((c + 2) % 3) * 16384, Bb + (c + 2) * 64, 384, t);
            CPA_COMMIT();
            MMA_CHUNK(smbase + FQB + c * 16384, smbase + FSB + (c % 3) * 16384, sacc);
        }

        // ---- scale + mask ----
        const float scl = 0.08838834764831845f;
#pragma unroll
        for (int mi = 0; mi < 4; mi++)
#pragma unroll
            for (int nj = 0; nj < 4; nj++) {
                const int cbase = warp_n * 32 + nj * 8 + (lane & 3) * 2;
                const bool mk0 = mk[cbase] != 0, mk1 = mk[cbase + 1] != 0;
                sacc[mi][nj][0] = mk0 ? -1e9f : sacc[mi][nj][0] * scl;
                sacc[mi][nj][1] = mk1 ? -1e9f : sacc[mi][nj][1] * scl;
                sacc[mi][nj][2] = mk0 ? -1e9f : sacc[mi][nj][2] * scl;
                sacc[mi][nj][3] = mk1 ? -1e9f : sacc[mi][nj][3] * scl;
            }

        // ---- per-warp row-max partials ----
#pragma unroll
        for (int mi = 0; mi < 4; mi++) {
            float mx0 = -1e30f, mx1 = -1e30f;
#pragma unroll
            for (int nj = 0; nj < 4; nj++) {
                mx0 = fmaxf(mx0, fmaxf(sacc[mi][nj][0], sacc[mi][nj][1]));
                mx1 = fmaxf(mx1, fmaxf(sacc[mi][nj][2], sacc[mi][nj][3]));
            }
            mx0 = fmaxf(mx0, __shfl_xor_sync(0xFFFFFFFFu, mx0, 1));
            mx0 = fmaxf(mx0, __shfl_xor_sync(0xFFFFFFFFu, mx0, 2));
            mx1 = fmaxf(mx1, __shfl_xor_sync(0xFFFFFFFFu, mx1, 1));
            mx1 = fmaxf(mx1, __shfl_xor_sync(0xFFFFFFFFu, mx1, 2));
            if ((lane & 3) == 0) {
                const int r = warp_m * 64 + mi * 16 + (lane >> 2);
                pmax[warp_n * 128 + r] = mx0;
                pmax[warp_n * 128 + r + 8] = mx1;
            }
        }
        __syncthreads();   // pmax ready; also: all warps done with S-phase SB reads

        // ---- prefetch V (overlaps softmax math): Vh0, Vh1, Vl0 ----
        cpa_tile(smbase + FSB,          Vt + (size_t)kt * 128,        3072, t); CPA_COMMIT();
        cpa_tile(smbase + FSB + 16384,  Vt + (size_t)kt * 128 + 64,   3072, t); CPA_COMMIT();
        cpa_tile(smbase + FSB + 32768,  Vt + 1024 + (size_t)kt * 128, 3072, t); CPA_COMMIT();

        // ---- P = exp(S - m_new), rescale O, partial row sums ----
#pragma unroll
        for (int mi = 0; mi < 4; mi++) {
            const int r0 = warp_m * 64 + mi * 16 + (lane >> 2), r1 = r0 + 8;
            const float mo0 = m_run[r0], mo1 = m_run[r1];
            float mn0 = fmaxf(fmaxf(pmax[r0], pmax[128 + r0]), fmaxf(pmax[256 + r0], pmax[384 + r0]));
            float mn1 = fmaxf(fmaxf(pmax[r1], pmax[128 + r1]), fmaxf(pmax[256 + r1], pmax[384 + r1]));
            mn0 = fmaxf(mn0, mo0); mn1 = fmaxf(mn1, mo1);
            const float f0 = __expf(mo0 - mn0), f1 = __expf(mo1 - mn1);
            float s0 = 0.f, s1 = 0.f;
#pragma unroll
            for (int nj = 0; nj < 4; nj++) {
                sacc[mi][nj][0] = __expf(sacc[mi][nj][0] - mn0); s0 += sacc[mi][nj][0];
                sacc[mi][nj][1] = __expf(sacc[mi][nj][1] - mn0); s0 += sacc[mi][nj][1];
                sacc[mi][nj][2] = __expf(sacc[mi][nj][2] - mn1); s1 += sacc[mi][nj][2];
                sacc[mi][nj][3] = __expf(sacc[mi][nj][3] - mn1); s1 += sacc[mi][nj][3];
                oacc[mi][nj][0] *= f0; oacc[mi][nj][1] *= f0;
                oacc[mi][nj][2] *= f1; oacc[mi][nj][3] *= f1;
            }
            s0 += __shfl_xor_sync(0xFFFFFFFFu, s0, 1); s0 += __shfl_xor_sync(0xFFFFFFFFu, s0, 2);
            s1 += __shfl_xor_sync(0xFFFFFFFFu, s1, 1); s1 += __shfl_xor_sync(0xFFFFFFFFu, s1, 2);
            if ((lane & 3) == 0) {
                psum[warp_n * 128 + r0] = s0;
                psum[warp_n * 128 + r1] = s1;
            }
        }
        __syncthreads();
        if (t < 128) {
            const float mo = m_run[t];
            float mn = fmaxf(fmaxf(pmax[t], pmax[128 + t]), fmaxf(pmax[256 + t], pmax[384 + t]));
            mn = fmaxf(mn, mo);
            l_run[t] = l_run[t] * __expf(mo - mn)
                     + psum[t] + psum[128 + t] + psum[256 + t] + psum[384 + t];
            m_run[t] = mn;
        }

        // ---- write P hi+lo (ALL warps, one pass) ----
        {
            const int hc = warp_n >> 1;             // which 64-col chunk this warp's cols fall in
            char* pbh = smt + FPB + hc * 16384;
            char* pbl = smt + FPB + 32768 + hc * 16384;
#pragma unroll
            for (int mi = 0; mi < 4; mi++)
#pragma unroll
                for (int nj = 0; nj < 4; nj++) {
                    const int r0 = warp_m * 64 + mi * 16 + (lane >> 2);
                    const int lc = (warp_n & 1) * 32 + nj * 8 + (lane & 3) * 2;
                    __nv_bfloat162 h0, h1, l0v, l1v;
                    bf hh, ll;
                    split_bf(sacc[mi][nj][0], hh, ll); h0.x = hh; l0v.x = ll;
                    split_bf(sacc[mi][nj][1], hh, ll); h0.y = hh; l0v.y = ll;
                    split_bf(sacc[mi][nj][2], hh, ll); h1.x = hh; l1v.x = ll;
                    split_bf(sacc[mi][nj][3], hh, ll); h1.y = hh; l1v.y = ll;
                    *(__nv_bfloat162*)(pbh + sw128(r0 * 128 + lc * 2)) = h0;
                    *(__nv_bfloat162*)(pbh + sw128((r0 + 8) * 128 + lc * 2)) = h1;
                    *(__nv_bfloat162*)(pbl + sw128(r0 * 128 + lc * 2)) = l0v;
                    *(__nv_bfloat162*)(pbl + sw128((r0 + 8) * 128 + lc * 2)) = l1v;
                }
        }
        __syncthreads();   // P tiles visible to all warps

        // ---- P·V: 6 MMAs, V-hi reused from smem for the P-lo term ----
        CPA_WAIT2();                                            // Vh0 ready
        MMA_CHUNK(smbase + FPB,          smbase + FSB, oacc);   // Phi0 · Vh0
        MMA_CHUNK(smbase + FPB + 32768,  smbase + FSB, oacc);   // Plo0 · Vh0
        __syncthreads();                                        // SB0 free
        cpa_tile(smbase + FSB, Vt + 1024 + (size_t)kt * 128 + 64, 3072, t);  // Vl1
        CPA_COMMIT();
        CPA_WAIT2();                                            // Vh1 ready
        MMA_CHUNK(smbase + FPB + 16384,  smbase + FSB + 16384, oacc);  // Phi1 · Vh1
        MMA_CHUNK(smbase + FPB + 49152,  smbase + FSB + 16384, oacc);  // Plo1 · Vh1
        CPA_WAIT1();                                            // Vl0 ready
        MMA_CHUNK(smbase + FPB,          smbase + FSB + 32768, oacc);  // Phi0 · Vl0
        CPA_WAIT0();                                            // Vl1 ready
        MMA_CHUNK(smbase + FPB + 16384,  smbase + FSB, oacc);          // Phi1 · Vl1
        __syncthreads();   // everyone done before next kt overwrites mk/SB/P
    }

    // ---- epilogue: O / l, split-store to ctx (hi|hi|lo) ----
    float inv0[4], inv1[4];
#pragma unroll
    for (int mi = 0; mi < 4; mi++) {
        const int r0 = warp_m * 64 + mi * 16 + (lane >> 2);
        inv0[mi] = 1.f / l_run[r0];
        inv1[mi] = 1.f / l_run[r0 + 8];
    }
    float* stg = (float*)smt;
    for (int cb = 0; cb < 4; cb++) {
        __syncthreads();
        if (warp_n == cb) {
#pragma unroll
            for (int mi = 0; mi < 4; mi++)
#pragma unroll
                for (int nj = 0; nj < 4; nj++) {
                    const int r  = warp_m * 64 + mi * 16 + (lane >> 2);
                    const int cc = nj * 8 + (lane & 3) * 2;
                    stg[r * 33 + cc]           = oacc[mi][nj][0] * inv0[mi];
                    stg[r * 33 + cc + 1]       = oacc[mi][nj][1] * inv0[mi];
                    stg[(r + 8) * 33 + cc]     = oacc[mi][nj][2] * inv1[mi];
                    stg[(r + 8) * 33 + cc + 1] = oacc[mi][nj][3] * inv1[mi];
                }
        }
        __syncthreads();
        const int row = t >> 1, c0 = (t & 1) * 16;
        const float* sr = stg + row * 33 + c0;
        const int n = cb * 32 + c0;
        bf* cd = ctx + ((size_t)b * SSZ + m0 + row) * 3072 + h * 128 + n;
        bf hi16[16], lo16[16];
#pragma unroll
        for (int c = 0; c < 16; c++) split_bf(sr[c], hi16[c], lo16[c]);
        uint4* hv = (uint4*)hi16; uint4* lv = (uint4*)lo16;
        *(uint4*)(cd) = hv[0];          *(uint4*)(cd + 8) = hv[1];
        *(uint4*)(cd + 1024) = hv[0];   *(uint4*)(cd + 1032) = hv[1];
        *(uint4*)(cd + 2048) = lv[0];   *(uint4*)(cd + 2056) = lv[1];
    }
}

// ---------------- prep kernels ----------------
__global__ __launch_bounds__(256) void split_act(const float* v, const float* k, const float* q)
{
    const float* s = blockIdx.z == 0 ? v : blockIdx.z == 1 ? k : q;
    bf* dst = g_xc[blockIdx.z];
    const size_t i = ((size_t)blockIdx.x * 256 + threadIdx.x) * 4;
    const size_t row = i >> 10, col = i & 1023;
    float4 x = *(const float4*)(s + i);
    bf h[4], l[4];
    split_bf(x.x, h[0], l[0]); split_bf(x.y, h[1], l[1]);
    split_bf(x.z, h[2], l[2]); split_bf(x.w, h[3], l[3]);
    bf* d = dst + row * 3072 + col;
    *(uint2*)(d) = *(uint2*)h;
    *(uint2*)(d + 1024) = *(uint2*)h;
    *(uint2*)(d + 2048) = *(uint2*)l;
}

__global__ void wsplit(const float* W, bf* Wc, int K, int N)
{
    __shared__ float sm[32][33];
    const int k0 = blockIdx.y * 32, n0 = blockIdx.x * 32;
    for (int r = threadIdx.y; r < 32; r += 8)
        sm[r][threadIdx.x] = W[(size_t)(k0 + r) * N + n0 + threadIdx.x];
    __syncthreads();
    for (int r = threadIdx.y; r < 32; r += 8) {
        bf hi, lo; split_bf(sm[threadIdx.x][r], hi, lo);
        bf* d = Wc + (size_t)(n0 + r) * 3 * K + k0 + threadIdx.x;
        d[0] = hi; d[K] = lo; d[2 * K] = hi;
    }
}

__global__ __launch_bounds__(128) void gate_apply(const float* Wg2, const float* bg2)
{
    const size_t row = blockIdx.x;
    const int d = threadIdx.x;
    const size_t o = row * 128 + d;
    float tv = g_gx[o] * g_gy[o];
    float s0 = tv * Wg2[d * 2], s1 = tv * Wg2[d * 2 + 1];
    const int lane = d & 31, w = d >> 5;
#pragma unroll
    for (int off = 16; off; off >>= 1) {
        s0 += __shfl_xor_sync(0xFFFFFFFFu, s0, off);
        s1 += __shfl_xor_sync(0xFFFFFFFFu, s1, off);
    }
    __shared__ float r0[4], r1[4];
    if (lane == 0) { r0[w] = s0; r1[w] = s1; }
    __syncthreads();
    float t0 = r0[0] + r0[1] + r0[2] + r0[3];
    float t1 = r1[0] + r1[1] + r1[2] + r1[3];
    float gk = 1.f / (1.f + __expf(-(t0 + bg2[0])));
    float gq = 1.f / (1.f + __expf(-(t1 + bg2[1])));
    bf hi, lo;
    split_bf(g_kh[o] * gk, hi, lo);
    bf* kd = g_kgc + row * 384 + d;                       // (hi,lo,hi)
    kd[0] = hi; kd[128] = lo; kd[256] = hi;
    split_bf(g_qh[o] * gq, hi, lo);
    bf* qd = g_qgc + row * 384 + d;                       // (hi,hi,lo)
    qd[0] = hi; qd[128] = hi; qd[256] = lo;
}

// ---------------- launch ----------------
#define TCSMEM 65536

extern "C" void kernel_launch(void* const* d_in, const int* in_sizes, int n_in,
                              void* d_out, int out_size)
{
    (void)in_sizes; (void)n_in; (void)out_size;
    const float* v  = (const float*)d_in[0];
    const float* k  = (const float*)d_in[1];
    const float* q  = (const float*)d_in[2];
    const unsigned char* mask = (const unsigned char*)d_in[3];
    const float* Wv = (const float*)d_in[4];  const float* bv = (const float*)d_in[5];
    const float* Wk = (const float*)d_in[6];  const float* bk = (const float*)d_in[7];
    const float* Wq = (const float*)d_in[8];  const float* bq = (const float*)d_in[9];
    const float* Wm = (const float*)d_in[10]; const float* bm = (const float*)d_in[11];
    const float* WgX = (const float*)d_in[12]; const float* bgX = (const float*)d_in[13];
    const float* WgY = (const float*)d_in[14]; const float* bgY = (const float*)d_in[15];
    const float* Wg2 = (const float*)d_in[16]; const float* bg2 = (const float*)d_in[17];
    float* outp = (float*)d_out;

    cudaFuncSetAttribute(tc_gemm<0>, cudaFuncAttributeMaxDynamicSharedMemorySize, TCSMEM);
    cudaFuncSetAttribute(tc_gemm<1>, cudaFuncAttributeMaxDynamicSharedMemorySize, TCSMEM);
    cudaFuncSetAttribute(tc_gemm<2>, cudaFuncAttributeMaxDynamicSharedMemorySize, TCSMEM);
    cudaFuncSetAttribute(tc_gemm<5>, cudaFuncAttributeMaxDynamicSharedMemorySize, TCSMEM);
    cudaFuncSetAttribute(flash_att,  cudaFuncAttributeMaxDynamicSharedMemorySize, FSMEM);

    bf* wc0; bf* wc1; bf* wc2; bf* wc3; bf* wg0; bf* wg1;
    bf* xc0; bf* xc1; bf* xc2;
    cudaGetSymbolAddress((void**)&wc0, g_wc);  wc1 = wc0 + (size_t)1024 * 3072;
    wc2 = wc1 + (size_t)1024 * 3072; wc3 = wc2 + (size_t)1024 * 3072;
    cudaGetSymbolAddress((void**)&wg0, g_wgc); wg1 = wg0 + (size_t)128 * 384;
    cudaGetSymbolAddress((void**)&xc0, g_xc);  xc1 = xc0 + (size_t)MT * 3072; xc2 = xc1 + (size_t)MT * 3072;
    float *kh, *qh, *gx, *gy;
    bf *khc, *qhc, *kgc, *qgc, *vtc, *ctxc;
    cudaGetSymbolAddress((void**)&kh, g_kh);   cudaGetSymbolAddress((void**)&qh, g_qh);
    cudaGetSymbolAddress((void**)&gx, g_gx);   cudaGetSymbolAddress((void**)&gy, g_gy);
    cudaGetSymbolAddress((void**)&khc, g_khc); cudaGetSymbolAddress((void**)&qhc, g_qhc);
    cudaGetSymbolAddress((void**)&kgc, g_kgc); cudaGetSymbolAddress((void**)&qgc, g_qgc);
    cudaGetSymbolAddress((void**)&vtc, g_vtc); cudaGetSymbolAddress((void**)&ctxc, g_ctxc);

    split_act<<<dim3(8192, 1, 3), 256>>>(v, k, q);
    wsplit<<<dim3(32, 32), dim3(32, 8)>>>(Wv, wc0, 1024, 1024);
    wsplit<<<dim3(32, 32), dim3(32, 8)>>>(Wk, wc1, 1024, 1024);
    wsplit<<<dim3(32, 32), dim3(32, 8)>>>(Wq, wc2, 1024, 1024);
    wsplit<<<dim3(32, 32), dim3(32, 8)>>>(Wm, wc3, 1024, 1024);
    wsplit<<<dim3(4, 4),   dim3(32, 8)>>>(WgX, wg0, 128, 128);
    wsplit<<<dim3(4, 4),   dim3(32, 8)>>>(WgY, wg1, 128, 128);

    GArgs a = {};
    // proj V -> vtc
    a.A = xc0; a.B = wc0; a.lda = 3072; a.ldb = 3072; a.bsA = 0; a.bsB = 0;
    a.K = 3072; a.bias = bv; a.oc = vtc;
    tc_gemm<0><<<dim3(64, 8, 1), 256, TCSMEM>>>(a);
    // proj K -> kh + khc
    a.B = wc1; a.bias = bk; a.of = kh; a.oc = khc; a.A = xc1;
    tc_gemm<1><<<dim3(64, 8, 1), 256, TCSMEM>>>(a);
    // proj Q -> qh + qhc
    a.B = wc2; a.bias = bq; a.of = qh; a.oc = qhc; a.A = xc2;
    tc_gemm<1><<<dim3(64, 8, 1), 256, TCSMEM>>>(a);
    // gate X / Y
    a.A = khc; a.B = wg0; a.lda = 384; a.ldb = 384; a.K = 384; a.bias = bgX; a.of = gx; a.oc = nullptr;
    tc_gemm<2><<<dim3(512, 1, 1), 256, TCSMEM>>>(a);
    a.A = qhc; a.B = wg1; a.bias = bgY; a.of = gy;
    tc_gemm<2><<<dim3(512, 1, 1), 256, TCSMEM>>>(a);

    gate_apply<<<BHZ * SSZ, 128>>>(Wg2, bg2);

    // fused scores+softmax+attV (v2)
    flash_att<<<dim3(8, 1, BHZ), 256, FSMEM>>>(qgc, kgc, vtc, mask, ctxc);

    // final
    a.A = ctxc; a.B = wc3; a.lda = 3072; a.ldb = 3072; a.bsA = 0; a.bsB = 0;
    a.K = 3072; a.bias = bm; a.of = outp; a.oc = nullptr;
    tc_gemm<5><<<dim3(64, 8, 1), 256, TCSMEM>>>(a);
}

// round 10
// speedup vs baseline: 1.5502x; 1.3692x over previous
#include <cuda_runtime.h>
#include <cuda_bf16.h>
#include <cstdint>
#include <math.h>

#define SSZ 1024
#define HSZ 8
#define BHZ 64
#define MT  8192
typedef __nv_bfloat16 bf;

// ---------------- scratch (device globals) ----------------
// All split tensors stored (hi | lo): per-term K wide each part.
__device__ __align__(16) bf    g_xc[3][(size_t)MT * 2048];      // acts, K=1024/part
__device__ __align__(16) bf    g_wc[4][(size_t)1024 * 2048];    // W^T: v,k,q,m
__device__ __align__(16) bf    g_wgc[2][(size_t)128 * 256];     // WgX^T, WgY^T (K=128/part)
__device__ __align__(16) bf    g_khc[(size_t)BHZ * SSZ * 256];  // proj K head-split
__device__ __align__(16) bf    g_qhc[(size_t)BHZ * SSZ * 256];
__device__ __align__(16) float g_gx[(size_t)BHZ * SSZ * 128];
__device__ __align__(16) float g_gy[(size_t)BHZ * SSZ * 128];
__device__ __align__(16) bf    g_kgc[(size_t)BHZ * SSZ * 256];  // gated k
__device__ __align__(16) bf    g_qgc[(size_t)BHZ * SSZ * 256];  // gated q
__device__ __align__(16) bf    g_vtc[(size_t)BHZ * 128 * 2048]; // v^T per head [bh][d][2S]
__device__ __align__(16) bf    g_ctxc[(size_t)MT * 2048];       // ctx

// ---------------- helpers ----------------
__device__ __forceinline__ uint32_t smem_u32(const void* p) {
    uint32_t a;
    asm("{ .reg .u64 t; cvta.to.shared.u64 t, %1; cvt.u32.u64 %0, t; }" : "=r"(a) : "l"(p));
    return a;
}
__device__ __forceinline__ uint32_t sw128(uint32_t o) { return o ^ ((o >> 3) & 0x70); }
__device__ __forceinline__ void split_bf(float v, bf& hi, bf& lo) {
    hi = __float2bfloat16(v);
    lo = __float2bfloat16(v - __bfloat162float(hi));
}
// async-load one 128x64 bf16 tile (128B rows, SW128) into smem
__device__ __forceinline__ void cpa_tile(uint32_t sdst, const bf* src, long ld, int t) {
#pragma unroll
    for (int r = 0; r < 4; r++) {
        const int it = t + r * 256;
        const int row = it >> 3, seg = it & 7;
        const uint32_t d = sdst + sw128(row * 128 + seg * 16);
        const bf* p = src + (size_t)row * ld + seg * 8;
        asm volatile("cp.async.cg.shared.global [%0], [%1], 16;" :: "r"(d), "l"(p));
    }
}
#define CPA_COMMIT() asm volatile("cp.async.commit_group;" ::: "memory")
#define CPA_WAIT2()  asm volatile("cp.async.wait_group 2;" ::: "memory")
#define CPA_WAIT1()  asm volatile("cp.async.wait_group 1;" ::: "memory")
#define CPA_WAIT0()  asm volatile("cp.async.wait_group 0;" ::: "memory")

// one 64-wide-K chunk of 128x128 mma.sync work
#define MMA_CHUNK(sA, sB, ACC)                                                           \
    {                                                                                    \
        _Pragma("unroll")                                                                \
        for (int ks = 0; ks < 4; ks++) {                                                 \
            const int kb = ks * 32;                                                      \
            uint32_t a[4][4], bfr[4][2];                                                 \
            _Pragma("unroll")                                                            \
            for (int mi = 0; mi < 4; mi++) {                                             \
                const uint32_t addr = (sA) + sw128((warp_m * 64 + mi * 16 + (lane & 15)) * 128 \
                                                   + kb + (lane >> 4) * 16);             \
                asm volatile("ldmatrix.sync.aligned.m8n8.x4.shared.b16 {%0,%1,%2,%3}, [%4];" \
                    : "=r"(a[mi][0]), "=r"(a[mi][1]), "=r"(a[mi][2]), "=r"(a[mi][3]) : "r"(addr)); \
            }                                                                            \
            _Pragma("unroll")                                                            \
            for (int jp = 0; jp < 2; jp++) {                                             \
                const uint32_t addr = (sB) + sw128((warp_n * 32 + jp * 16 + ((lane >> 4) & 1) * 8 \
                                                    + (lane & 7)) * 128                  \
                                                   + kb + ((lane >> 3) & 1) * 16);       \
                asm volatile("ldmatrix.sync.aligned.m8n8.x4.shared.b16 {%0,%1,%2,%3}, [%4];" \
                    : "=r"(bfr[jp * 2][0]), "=r"(bfr[jp * 2][1]),                        \
                      "=r"(bfr[jp * 2 + 1][0]), "=r"(bfr[jp * 2 + 1][1]) : "r"(addr));   \
            }                                                                            \
            _Pragma("unroll")                                                            \
            for (int mi = 0; mi < 4; mi++)                                               \
                _Pragma("unroll")                                                        \
                for (int nj = 0; nj < 4; nj++)                                           \
                    asm volatile(                                                        \
                        "mma.sync.aligned.m16n8k16.row.col.f32.bf16.bf16.f32 "           \
                        "{%0,%1,%2,%3}, {%4,%5,%6,%7}, {%8,%9}, {%0,%1,%2,%3};"          \
                        : "+f"(ACC[mi][nj][0]), "+f"(ACC[mi][nj][1]),                    \
                          "+f"(ACC[mi][nj][2]), "+f"(ACC[mi][nj][3])                     \
                        : "r"(a[mi][0]), "r"(a[mi][1]), "r"(a[mi][2]), "r"(a[mi][3]),    \
                          "r"(bfr[nj][0]), "r"(bfr[nj][1]));                             \
        }                                                                                \
    }

// ---------------- mma.sync GEMM, 3-pass split: C = A*B^T ----------------
// A stored (hi|lo), B stored (hi|lo). Passes pair (Ahi,Bhi),(Ahi,Blo),(Alo,Bhi).
struct GArgs {
    const bf *A, *B;
    long lda, ldb, bsA, bsB;
    long loA, loB;           // element offset of lo part
    int nchp;                // 64-wide chunks per pass
    const float* bias;
    float* of;
    bf* oc;
};

// MODE: 0=projV(transposed split) 1=projKQ(split) 2=gate(f32) 5=final
template<int MODE>
__global__ __launch_bounds__(256) void tc_gemm(GArgs g)
{
    extern __shared__ __align__(16) char smt[];
    const uint32_t smbase = smem_u32(smt);
    const int t = threadIdx.x;
    const int lane = t & 31, wid = t >> 5;
    const int warp_m = wid >> 2, warp_n = wid & 3;

    const int m0 = blockIdx.x * 128;
    const int n0 = blockIdx.y * 128;
    const int bz = blockIdx.z;
    const bf* Ab = g.A + (size_t)bz * g.bsA + (size_t)m0 * g.lda;
    const bf* Bb = g.B + (size_t)bz * g.bsB + (size_t)n0 * g.ldb;

    float acc[4][4][4];
#pragma unroll
    for (int i = 0; i < 4; i++)
#pragma unroll
        for (int j = 0; j < 4; j++)
#pragma unroll
            for (int c = 0; c < 4; c++) acc[i][j][c] = 0.f;

    const int nchp = g.nchp;
    const int nch = nchp * 3;

#define ACHUNK(j) (Ab + ((j) >= 2 * nchp ? g.loA : 0) + (size_t)((j) % nchp) * 64)
#define BCHUNK(j) (Bb + (((j) >= nchp && (j) < 2 * nchp) ? g.loB : 0) + (size_t)((j) % nchp) * 64)
#define PREFETCH(i)                                                          \
    {                                                                        \
        cpa_tile(smbase + ((i) & 1) * 32768,         ACHUNK(i), g.lda, t);   \
        cpa_tile(smbase + ((i) & 1) * 32768 + 16384, BCHUNK(i), g.ldb, t);   \
    }

    PREFETCH(0);
    CPA_COMMIT();
    if (nch > 1) PREFETCH(1);
    CPA_COMMIT();

    for (int i = 0; i < nch; i++) {
        CPA_WAIT1();
        __syncthreads();
        const uint32_t sA = smbase + (i & 1) * 32768;
        const uint32_t sB = sA + 16384;
        MMA_CHUNK(sA, sB, acc);
        __syncthreads();
        if (i + 2 < nch) PREFETCH(i + 2);
        CPA_COMMIT();
    }
    CPA_WAIT0();
#undef PREFETCH
#undef ACHUNK
#undef BCHUNK

    // ---------------- epilogue: 4 col-blocks of 32 through smem staging ----------------
    float* stg = (float*)smt;   // 128 x 33 fp32
    for (int cb = 0; cb < 4; cb++) {
        __syncthreads();
        if (warp_n == cb) {
#pragma unroll
            for (int mi = 0; mi < 4; mi++)
#pragma unroll
                for (int nj = 0; nj < 4; nj++) {
                    const int r  = warp_m * 64 + mi * 16 + (lane >> 2);
                    const int cc = nj * 8 + (lane & 3) * 2;
                    stg[r * 33 + cc]           = acc[mi][nj][0];
                    stg[r * 33 + cc + 1]       = acc[mi][nj][1];
                    stg[(r + 8) * 33 + cc]     = acc[mi][nj][2];
                    stg[(r + 8) * 33 + cc + 1] = acc[mi][nj][3];
                }
        }
        __syncthreads();

        if (MODE == 0) {
            // v^T: per-head [bh][d][2S] (hi|lo)
            const int dloc = t & 31, soff = (t >> 5) * 16;
            const int b = m0 >> 10, h = blockIdx.y, d = cb * 32 + dloc;
            const int scol = (m0 & 1023) + soff;
            bf hi16[16], lo16[16];
#pragma unroll
            for (int i2 = 0; i2 < 16; i2++) {
                float v = stg[(soff + i2) * 33 + dloc] + g.bias[n0 + d];
                split_bf(v, hi16[i2], lo16[i2]);
            }
            bf* dst = g.oc + ((size_t)(b * HSZ + h) * 128 + d) * 2048 + scol;
            uint4* hv = (uint4*)hi16; uint4* lv = (uint4*)lo16;
            *(uint4*)(dst) = hv[0];          *(uint4*)(dst + 8) = hv[1];
            *(uint4*)(dst + 1024) = lv[0];   *(uint4*)(dst + 1032) = lv[1];
        } else {
            const int row = t >> 1, c0 = (t & 1) * 16;
            const float* sr = stg + row * 33 + c0;
            if (MODE == 1) {
                const int h = blockIdx.y, m = m0 + row, b = m >> 10, s = m & 1023;
                const int d0 = cb * 32 + c0;
                bf* cd = g.oc + ((size_t)(b * HSZ + h) * SSZ + s) * 256 + d0;
                bf hi16[16], lo16[16];
#pragma unroll
                for (int c = 0; c < 16; c++)
                    split_bf(sr[c] + g.bias[n0 + d0 + c], hi16[c], lo16[c]);
                uint4* hv = (uint4*)hi16; uint4* lv = (uint4*)lo16;
                *(uint4*)(cd) = hv[0];        *(uint4*)(cd + 8) = hv[1];
                *(uint4*)(cd + 128) = lv[0];  *(uint4*)(cd + 136) = lv[1];
            } else if (MODE == 2) {
                float* fd = g.of + (size_t)(m0 + row) * 128 + cb * 32 + c0;
#pragma unroll
                for (int c = 0; c < 16; c += 4) {
                    float4 w;
                    w.x = sr[c]     + g.bias[cb * 32 + c0 + c];
                    w.y = sr[c + 1] + g.bias[cb * 32 + c0 + c + 1];
                    w.z = sr[c + 2] + g.bias[cb * 32 + c0 + c + 2];
                    w.w = sr[c + 3] + g.bias[cb * 32 + c0 + c + 3];
                    *(float4*)(fd + c) = w;
                }
            } else {
                const int nt = n0 + cb * 32 + c0;
                float* fd = g.of + (size_t)(m0 + row) * 1024 + nt;
#pragma unroll
                for (int c = 0; c < 16; c += 4) {
                    float4 w;
                    w.x = sr[c]     + g.bias[nt + c];
                    w.y = sr[c + 1] + g.bias[nt + c + 1];
                    w.z = sr[c + 2] + g.bias[nt + c + 2];
                    w.w = sr[c + 3] + g.bias[nt + c + 3];
                    *(float4*)(fd + c) = w;
                }
            }
        }
    }
}

// ---------------- fused flash attention v3 ----------------
// Q resident (4 tiles, hi|lo), K streams 4 unique chunks per key-tile (6 MMAs),
// V streams 4 unique chunks (6 MMAs). Syncs after every wait (cp.async visibility).
#define FQB  0
#define FPB  65536
#define FSB  131072
#define FSM_PMAX 180224
#define FSM_PSUM (180224 + 2048)
#define FSM_MRUN (180224 + 4096)
#define FSM_LRUN (180224 + 4608)
#define FSM_MASK (180224 + 5120)
#define FSMEM    (180224 + 5376)

__global__ __launch_bounds__(256) void flash_att(
    const bf* __restrict__ qg, const bf* __restrict__ kg, const bf* __restrict__ vt,
    const unsigned char* __restrict__ mask, bf* __restrict__ ctx)
{
    extern __shared__ __align__(16) char smt[];
    const uint32_t smbase = smem_u32(smt);
    float* pmax = (float*)(smt + FSM_PMAX);     // [4][128]
    float* psum = (float*)(smt + FSM_PSUM);     // [4][128]
    float* m_run = (float*)(smt + FSM_MRUN);    // [128]
    float* l_run = (float*)(smt + FSM_LRUN);    // [128]
    unsigned char* mk = (unsigned char*)(smt + FSM_MASK);

    const int t = threadIdx.x, lane = t & 31, wid = t >> 5;
    const int warp_m = wid >> 2, warp_n = wid & 3;
    const int m0 = blockIdx.x * 128;
    const int bh = blockIdx.z, b = bh >> 3, h = bh & 7;

    const bf* Aq = qg + (size_t)bh * SSZ * 256 + (size_t)m0 * 256;
    const bf* Bk = kg + (size_t)bh * SSZ * 256;
    const bf* Vt = vt + (size_t)bh * 128 * 2048;

    // Q resident: Qhi0, Qhi1, Qlo0, Qlo1
#pragma unroll
    for (int c = 0; c < 4; c++)
        cpa_tile(smbase + FQB + c * 16384, Aq + c * 64, 256, t);
    CPA_COMMIT();

    float oacc[4][4][4];
#pragma unroll
    for (int i = 0; i < 4; i++)
#pragma unroll
        for (int j = 0; j < 4; j++)
#pragma unroll
            for (int c = 0; c < 4; c++) oacc[i][j][c] = 0.f;

    if (t < 128) { m_run[t] = -1e30f; l_run[t] = 0.f; }
    CPA_WAIT0();
    __syncthreads();

    for (int kt = 0; kt < 8; kt++) {
        if (t < 128) mk[t] = mask[b * SSZ + kt * 128 + t];
        const bf* Bb = Bk + (size_t)(kt * 128) * 256;

        float sacc[4][4][4];
#pragma unroll
        for (int i = 0; i < 4; i++)
#pragma unroll
            for (int j = 0; j < 4; j++)
#pragma unroll
                for (int c = 0; c < 4; c++) sacc[i][j][c] = 0.f;

        // ---- S phase: stream Khi0,Khi1,Klo0,Klo1; 6 MMAs vs resident Q ----
        cpa_tile(smbase + FSB,         Bb,       256, t); CPA_COMMIT();   // Khi0 -> b0
        cpa_tile(smbase + FSB + 16384, Bb + 64,  256, t); CPA_COMMIT();   // Khi1 -> b1
        cpa_tile(smbase + FSB + 32768, Bb + 128, 256, t); CPA_COMMIT();   // Klo0 -> b2
        CPA_WAIT2(); __syncthreads();                                      // Khi0 ready
        MMA_CHUNK(smbase + FQB,         smbase + FSB, sacc);               // Qhi0·Khi0
        MMA_CHUNK(smbase + FQB + 32768, smbase + FSB, sacc);               // Qlo0·Khi0
        __syncthreads();                                                   // b0 free
        cpa_tile(smbase + FSB, Bb + 192, 256, t); CPA_COMMIT();            // Klo1 -> b0
        CPA_WAIT2(); __syncthreads();                                      // Khi1 ready
        MMA_CHUNK(smbase + FQB + 16384, smbase + FSB + 16384, sacc);       // Qhi1·Khi1
        MMA_CHUNK(smbase + FQB + 49152, smbase + FSB + 16384, sacc);       // Qlo1·Khi1
        CPA_WAIT1(); __syncthreads();                                      // Klo0 ready
        MMA_CHUNK(smbase + FQB,         smbase + FSB + 32768, sacc);       // Qhi0·Klo0
        CPA_WAIT0(); __syncthreads();                                      // Klo1 ready
        MMA_CHUNK(smbase + FQB + 16384, smbase + FSB, sacc);               // Qhi1·Klo1
        __syncthreads();

        // ---- scale + mask ----
        const float scl = 0.08838834764831845f;
#pragma unroll
        for (int mi = 0; mi < 4; mi++)
#pragma unroll
            for (int nj = 0; nj < 4; nj++) {
                const int cbase = warp_n * 32 + nj * 8 + (lane & 3) * 2;
                const bool mk0 = mk[cbase] != 0, mk1 = mk[cbase + 1] != 0;
                sacc[mi][nj][0] = mk0 ? -1e9f : sacc[mi][nj][0] * scl;
                sacc[mi][nj][1] = mk1 ? -1e9f : sacc[mi][nj][1] * scl;
                sacc[mi][nj][2] = mk0 ? -1e9f : sacc[mi][nj][2] * scl;
                sacc[mi][nj][3] = mk1 ? -1e9f : sacc[mi][nj][3] * scl;
            }

        // ---- per-warp row-max partials ----
#pragma unroll
        for (int mi = 0; mi < 4; mi++) {
            float mx0 = -1e30f, mx1 = -1e30f;
#pragma unroll
            for (int nj = 0; nj < 4; nj++) {
                mx0 = fmaxf(mx0, fmaxf(sacc[mi][nj][0], sacc[mi][nj][1]));
                mx1 = fmaxf(mx1, fmaxf(sacc[mi][nj][2], sacc[mi][nj][3]));
            }
            mx0 = fmaxf(mx0, __shfl_xor_sync(0xFFFFFFFFu, mx0, 1));
            mx0 = fmaxf(mx0, __shfl_xor_sync(0xFFFFFFFFu, mx0, 2));
            mx1 = fmaxf(mx1, __shfl_xor_sync(0xFFFFFFFFu, mx1, 1));
            mx1 = fmaxf(mx1, __shfl_xor_sync(0xFFFFFFFFu, mx1, 2));
            if ((lane & 3) == 0) {
                const int r = warp_m * 64 + mi * 16 + (lane >> 2);
                pmax[warp_n * 128 + r] = mx0;
                pmax[warp_n * 128 + r + 8] = mx1;
            }
        }
        __syncthreads();   // pmax ready; SB free

        // ---- prefetch V (overlaps softmax math): Vh0, Vh1, Vl0 ----
        cpa_tile(smbase + FSB,          Vt + (size_t)kt * 128,        2048, t); CPA_COMMIT();
        cpa_tile(smbase + FSB + 16384,  Vt + (size_t)kt * 128 + 64,   2048, t); CPA_COMMIT();
        cpa_tile(smbase + FSB + 32768,  Vt + 1024 + (size_t)kt * 128, 2048, t); CPA_COMMIT();

        // ---- P = exp(S - m_new), rescale O, partial row sums ----
#pragma unroll
        for (int mi = 0; mi < 4; mi++) {
            const int r0 = warp_m * 64 + mi * 16 + (lane >> 2), r1 = r0 + 8;
            const float mo0 = m_run[r0], mo1 = m_run[r1];
            float mn0 = fmaxf(fmaxf(pmax[r0], pmax[128 + r0]), fmaxf(pmax[256 + r0], pmax[384 + r0]));
            float mn1 = fmaxf(fmaxf(pmax[r1], pmax[128 + r1]), fmaxf(pmax[256 + r1], pmax[384 + r1]));
            mn0 = fmaxf(mn0, mo0); mn1 = fmaxf(mn1, mo1);
            const float f0 = __expf(mo0 - mn0), f1 = __expf(mo1 - mn1);
            float s0 = 0.f, s1 = 0.f;
#pragma unroll
            for (int nj = 0; nj < 4; nj++) {
                sacc[mi][nj][0] = __expf(sacc[mi][nj][0] - mn0); s0 += sacc[mi][nj][0];
                sacc[mi][nj][1] = __expf(sacc[mi][nj][1] - mn0); s0 += sacc[mi][nj][1];
                sacc[mi][nj][2] = __expf(sacc[mi][nj][2] - mn1); s1 += sacc[mi][nj][2];
                sacc[mi][nj][3] = __expf(sacc[mi][nj][3] - mn1); s1 += sacc[mi][nj][3];
                oacc[mi][nj][0] *= f0; oacc[mi][nj][1] *= f0;
                oacc[mi][nj][2] *= f1; oacc[mi][nj][3] *= f1;
            }
            s0 += __shfl_xor_sync(0xFFFFFFFFu, s0, 1); s0 += __shfl_xor_sync(0xFFFFFFFFu, s0, 2);
            s1 += __shfl_xor_sync(0xFFFFFFFFu, s1, 1); s1 += __shfl_xor_sync(0xFFFFFFFFu, s1, 2);
            if ((lane & 3) == 0) {
                psum[warp_n * 128 + r0] = s0;
                psum[warp_n * 128 + r1] = s1;
            }
        }
        __syncthreads();
        if (t < 128) {
            const float mo = m_run[t];
            float mn = fmaxf(fmaxf(pmax[t], pmax[128 + t]), fmaxf(pmax[256 + t], pmax[384 + t]));
            mn = fmaxf(mn, mo);
            l_run[t] = l_run[t] * __expf(mo - mn)
                     + psum[t] + psum[128 + t] + psum[256 + t] + psum[384 + t];
            m_run[t] = mn;
        }

        // ---- write P hi+lo (ALL warps, one pass) ----
        {
            const int hc = warp_n >> 1;
            char* pbh = smt + FPB + hc * 16384;
            char* pbl = smt + FPB + 32768 + hc * 16384;
#pragma unroll
            for (int mi = 0; mi < 4; mi++)
#pragma unroll
                for (int nj = 0; nj < 4; nj++) {
                    const int r0 = warp_m * 64 + mi * 16 + (lane >> 2);
                    const int lc = (warp_n & 1) * 32 + nj * 8 + (lane & 3) * 2;
                    __nv_bfloat162 h0, h1, l0v, l1v;
                    bf hh, ll;
                    split_bf(sacc[mi][nj][0], hh, ll); h0.x = hh; l0v.x = ll;
                    split_bf(sacc[mi][nj][1], hh, ll); h0.y = hh; l0v.y = ll;
                    split_bf(sacc[mi][nj][2], hh, ll); h1.x = hh; l1v.x = ll;
                    split_bf(sacc[mi][nj][3], hh, ll); h1.y = hh; l1v.y = ll;
                    *(__nv_bfloat162*)(pbh + sw128(r0 * 128 + lc * 2)) = h0;
                    *(__nv_bfloat162*)(pbh + sw128((r0 + 8) * 128 + lc * 2)) = h1;
                    *(__nv_bfloat162*)(pbl + sw128(r0 * 128 + lc * 2)) = l0v;
                    *(__nv_bfloat162*)(pbl + sw128((r0 + 8) * 128 + lc * 2)) = l1v;
                }
        }
        __syncthreads();   // P tiles visible

        // ---- P·V: 6 MMAs over 4 streamed V chunks ----
        CPA_WAIT2(); __syncthreads();                                   // Vh0 ready
        MMA_CHUNK(smbase + FPB,          smbase + FSB, oacc);           // Phi0·Vh0
        MMA_CHUNK(smbase + FPB + 32768,  smbase + FSB, oacc);           // Plo0·Vh0
        __syncthreads();                                                // SB0 free
        cpa_tile(smbase + FSB, Vt + 1024 + (size_t)kt * 128 + 64, 2048, t);  // Vl1
        CPA_COMMIT();
        CPA_WAIT2(); __syncthreads();                                   // Vh1 ready
        MMA_CHUNK(smbase + FPB + 16384,  smbase + FSB + 16384, oacc);   // Phi1·Vh1
        MMA_CHUNK(smbase + FPB + 49152,  smbase + FSB + 16384, oacc);   // Plo1·Vh1
        CPA_WAIT1(); __syncthreads();                                   // Vl0 ready
        MMA_CHUNK(smbase + FPB,          smbase + FSB + 32768, oacc);   // Phi0·Vl0
        CPA_WAIT0(); __syncthreads();                                   // Vl1 ready
        MMA_CHUNK(smbase + FPB + 16384,  smbase + FSB, oacc);           // Phi1·Vl1
        __syncthreads();   // done before next kt overwrites mk/SB/P
    }

    // ---- epilogue: O / l, split-store to ctx (hi|lo) ----
    float inv0[4], inv1[4];
#pragma unroll
    for (int mi = 0; mi < 4; mi++) {
        const int r0 = warp_m * 64 + mi * 16 + (lane >> 2);
        inv0[mi] = 1.f / l_run[r0];
        inv1[mi] = 1.f / l_run[r0 + 8];
    }
    float* stg = (float*)smt;
    for (int cb = 0; cb < 4; cb++) {
        __syncthreads();
        if (warp_n == cb) {
#pragma unroll
            for (int mi = 0; mi < 4; mi++)
#pragma unroll
                for (int nj = 0; nj < 4; nj++) {
                    const int r  = warp_m * 64 + mi * 16 + (lane >> 2);
                    const int cc = nj * 8 + (lane & 3) * 2;
                    stg[r * 33 + cc]           = oacc[mi][nj][0] * inv0[mi];
                    stg[r * 33 + cc + 1]       = oacc[mi][nj][1] * inv0[mi];
                    stg[(r + 8) * 33 + cc]     = oacc[mi][nj][2] * inv1[mi];
                    stg[(r + 8) * 33 + cc + 1] = oacc[mi][nj][3] * inv1[mi];
                }
        }
        __syncthreads();
        const int row = t >> 1, c0 = (t & 1) * 16;
        const float* sr = stg + row * 33 + c0;
        const int n = cb * 32 + c0;
        bf* cd = ctx + ((size_t)b * SSZ + m0 + row) * 2048 + h * 128 + n;
        bf hi16[16], lo16[16];
#pragma unroll
        for (int c = 0; c < 16; c++) split_bf(sr[c], hi16[c], lo16[c]);
        uint4* hv = (uint4*)hi16; uint4* lv = (uint4*)lo16;
        *(uint4*)(cd) = hv[0];          *(uint4*)(cd + 8) = hv[1];
        *(uint4*)(cd + 1024) = lv[0];   *(uint4*)(cd + 1032) = lv[1];
    }
}

// ---------------- prep kernels ----------------
__global__ __launch_bounds__(256) void split_act(const float* v, const float* k, const float* q)
{
    const float* s = blockIdx.z == 0 ? v : blockIdx.z == 1 ? k : q;
    bf* dst = g_xc[blockIdx.z];
    const size_t i = ((size_t)blockIdx.x * 256 + threadIdx.x) * 4;
    const size_t row = i >> 10, col = i & 1023;
    float4 x = *(const float4*)(s + i);
    bf h[4], l[4];
    split_bf(x.x, h[0], l[0]); split_bf(x.y, h[1], l[1]);
    split_bf(x.z, h[2], l[2]); split_bf(x.w, h[3], l[3]);
    bf* d = dst + row * 2048 + col;
    *(uint2*)(d) = *(uint2*)h;
    *(uint2*)(d + 1024) = *(uint2*)l;
}

__global__ void wsplit(const float* W, bf* Wc, int K, int N)
{
    __shared__ float sm[32][33];
    const int k0 = blockIdx.y * 32, n0 = blockIdx.x * 32;
    for (int r = threadIdx.y; r < 32; r += 8)
        sm[r][threadIdx.x] = W[(size_t)(k0 + r) * N + n0 + threadIdx.x];
    __syncthreads();
    for (int r = threadIdx.y; r < 32; r += 8) {
        bf hi, lo; split_bf(sm[threadIdx.x][r], hi, lo);
        bf* d = Wc + (size_t)(n0 + r) * 2 * K + k0 + threadIdx.x;
        d[0] = hi; d[K] = lo;
    }
}

__global__ __launch_bounds__(128) void gate_apply(const float* Wg2, const float* bg2)
{
    const size_t row = blockIdx.x;
    const int d = threadIdx.x;
    const size_t o = row * 128 + d;
    float tv = g_gx[o] * g_gy[o];
    float s0 = tv * Wg2[d * 2], s1 = tv * Wg2[d * 2 + 1];
    const int lane = d & 31, w = d >> 5;
#pragma unroll
    for (int off = 16; off; off >>= 1) {
        s0 += __shfl_xor_sync(0xFFFFFFFFu, s0, off);
        s1 += __shfl_xor_sync(0xFFFFFFFFu, s1, off);
    }
    __shared__ float r0[4], r1[4];
    if (lane == 0) { r0[w] = s0; r1[w] = s1; }
    __syncthreads();
    float t0 = r0[0] + r0[1] + r0[2] + r0[3];
    float t1 = r1[0] + r1[1] + r1[2] + r1[3];
    float gk = 1.f / (1.f + __expf(-(t0 + bg2[0])));
    float gq = 1.f / (1.f + __expf(-(t1 + bg2[1])));
    // reconstruct k,q from split (hi+lo), gate, re-split
    const size_t rb = row * 256 + d;
    float kv = __bfloat162float(g_khc[rb]) + __bfloat162float(g_khc[rb + 128]);
    float qv = __bfloat162float(g_qhc[rb]) + __bfloat162float(g_qhc[rb + 128]);
    bf hi, lo;
    split_bf(kv * gk, hi, lo);
    g_kgc[rb] = hi; g_kgc[rb + 128] = lo;
    split_bf(qv * gq, hi, lo);
    g_qgc[rb] = hi; g_qgc[rb + 128] = lo;
}

// ---------------- launch ----------------
#define TCSMEM 65536

extern "C" void kernel_launch(void* const* d_in, const int* in_sizes, int n_in,
                              void* d_out, int out_size)
{
    (void)in_sizes; (void)n_in; (void)out_size;
    const float* v  = (const float*)d_in[0];
    const float* k  = (const float*)d_in[1];
    const float* q  = (const float*)d_in[2];
    const unsigned char* mask = (const unsigned char*)d_in[3];
    const float* Wv = (const float*)d_in[4];  const float* bv = (const float*)d_in[5];
    const float* Wk = (const float*)d_in[6];  const float* bk = (const float*)d_in[7];
    const float* Wq = (const float*)d_in[8];  const float* bq = (const float*)d_in[9];
    const float* Wm = (const float*)d_in[10]; const float* bm = (const float*)d_in[11];
    const float* WgX = (const float*)d_in[12]; const float* bgX = (const float*)d_in[13];
    const float* WgY = (const float*)d_in[14]; const float* bgY = (const float*)d_in[15];
    const float* Wg2 = (const float*)d_in[16]; const float* bg2 = (const float*)d_in[17];
    float* outp = (float*)d_out;

    cudaFuncSetAttribute(tc_gemm<0>, cudaFuncAttributeMaxDynamicSharedMemorySize, TCSMEM);
    cudaFuncSetAttribute(tc_gemm<1>, cudaFuncAttributeMaxDynamicSharedMemorySize, TCSMEM);
    cudaFuncSetAttribute(tc_gemm<2>, cudaFuncAttributeMaxDynamicSharedMemorySize, TCSMEM);
    cudaFuncSetAttribute(tc_gemm<5>, cudaFuncAttributeMaxDynamicSharedMemorySize, TCSMEM);
    cudaFuncSetAttribute(flash_att,  cudaFuncAttributeMaxDynamicSharedMemorySize, FSMEM);

    bf* wc0; bf* wc1; bf* wc2; bf* wc3; bf* wg0; bf* wg1;
    bf* xc0; bf* xc1; bf* xc2;
    cudaGetSymbolAddress((void**)&wc0, g_wc);  wc1 = wc0 + (size_t)1024 * 2048;
    wc2 = wc1 + (size_t)1024 * 2048; wc3 = wc2 + (size_t)1024 * 2048;
    cudaGetSymbolAddress((void**)&wg0, g_wgc); wg1 = wg0 + (size_t)128 * 256;
    cudaGetSymbolAddress((void**)&xc0, g_xc);  xc1 = xc0 + (size_t)MT * 2048; xc2 = xc1 + (size_t)MT * 2048;
    float *gx, *gy;
    bf *khc, *qhc, *kgc, *qgc, *vtc, *ctxc;
    cudaGetSymbolAddress((void**)&gx, g_gx);   cudaGetSymbolAddress((void**)&gy, g_gy);
    cudaGetSymbolAddress((void**)&khc, g_khc); cudaGetSymbolAddress((void**)&qhc, g_qhc);
    cudaGetSymbolAddress((void**)&kgc, g_kgc); cudaGetSymbolAddress((void**)&qgc, g_qgc);
    cudaGetSymbolAddress((void**)&vtc, g_vtc); cudaGetSymbolAddress((void**)&ctxc, g_ctxc);

    // Launch order: makes launch #6 = tc_gemm<0> so ncu (-s 5 -c 1) profiles the engine.
    wsplit<<<dim3(32, 32), dim3(32, 8)>>>(Wv, wc0, 1024, 1024);   // 1
    wsplit<<<dim3(32, 32), dim3(32, 8)>>>(Wk, wc1, 1024, 1024);   // 2
    wsplit<<<dim3(32, 32), dim3(32, 8)>>>(Wq, wc2, 1024, 1024);   // 3
    wsplit<<<dim3(32, 32), dim3(32, 8)>>>(Wm, wc3, 1024, 1024);   // 4
    split_act<<<dim3(8192, 1, 3), 256>>>(v, k, q);                 // 5

    GArgs a = {};
    // 6: proj V -> vtc (PROFILED)
    a.A = xc0; a.B = wc0; a.lda = 2048; a.ldb = 2048; a.bsA = 0; a.bsB = 0;
    a.loA = 1024; a.loB = 1024; a.nchp = 16; a.bias = bv; a.oc = vtc;
    tc_gemm<0><<<dim3(64, 8, 1), 256, TCSMEM>>>(a);

    wsplit<<<dim3(4, 4), dim3(32, 8)>>>(WgX, wg0, 128, 128);       // 7
    wsplit<<<dim3(4, 4), dim3(32, 8)>>>(WgY, wg1, 128, 128);       // 8

    // proj K / Q -> khc / qhc
    a.B = wc1; a.bias = bk; a.oc = khc; a.A = xc1;
    tc_gemm<1><<<dim3(64, 8, 1), 256, TCSMEM>>>(a);
    a.B = wc2; a.bias = bq; a.oc = qhc; a.A = xc2;
    tc_gemm<1><<<dim3(64, 8, 1), 256, TCSMEM>>>(a);

    // gate X / Y
    a.A = khc; a.B = wg0; a.lda = 256; a.ldb = 256; a.loA = 128; a.loB = 128;
    a.nchp = 2; a.bias = bgX; a.of = gx; a.oc = nullptr;
    tc_gemm<2><<<dim3(512, 1, 1), 256, TCSMEM>>>(a);
    a.A = qhc; a.B = wg1; a.bias = bgY; a.of = gy;
    tc_gemm<2><<<dim3(512, 1, 1), 256, TCSMEM>>>(a);

    gate_apply<<<BHZ * SSZ, 128>>>(Wg2, bg2);

    // fused scores+softmax+attV (v3)
    flash_att<<<dim3(8, 1, BHZ), 256, FSMEM>>>(qgc, kgc, vtc, mask, ctxc);

    // final
    a.A = ctxc; a.B = wc3; a.lda = 2048; a.ldb = 2048; a.loA = 1024; a.loB = 1024;
    a.nchp = 16; a.bias = bm; a.of = outp; a.oc = nullptr;
    tc_gemm<5><<<dim3(64, 8, 1), 256, TCSMEM>>>(a);
}

// round 13
// speedup vs baseline: 1.6772x; 1.0819x over previous
#include <cuda_runtime.h>
#include <cuda_bf16.h>
#include <cstdint>
#include <math.h>

#define SSZ 1024
#define HSZ 8
#define BHZ 64
#define MT  8192
typedef __nv_bfloat16 bf;

// ---------------- scratch (device globals) ----------------
__device__ __align__(16) bf    g_xc[3][(size_t)MT * 2048];      // acts (hi|lo)
__device__ __align__(16) bf    g_wc[4][(size_t)1024 * 2048];    // W^T (hi|lo): v,k,q,m
__device__ __align__(16) bf    g_wgc[2][(size_t)128 * 256];     // WgX^T, WgY^T (hi|lo)
__device__ __align__(16) bf    g_khc[(size_t)BHZ * SSZ * 256];
__device__ __align__(16) bf    g_qhc[(size_t)BHZ * SSZ * 256];
__device__ __align__(16) float g_gx[(size_t)BHZ * SSZ * 128];
__device__ __align__(16) float g_gy[(size_t)BHZ * SSZ * 128];
__device__ __align__(16) bf    g_kgc[(size_t)BHZ * SSZ * 256];
__device__ __align__(16) bf    g_qgc[(size_t)BHZ * SSZ * 256];
__device__ __align__(16) bf    g_vtc[(size_t)BHZ * 128 * 2048]; // v^T [bh][d][2S]
__device__ __align__(16) bf    g_ctxc[(size_t)MT * 2048];

// ---------------- helpers ----------------
__device__ __forceinline__ uint32_t smem_u32(const void* p) {
    uint32_t a;
    asm("{ .reg .u64 t; cvta.to.shared.u64 t, %1; cvt.u32.u64 %0, t; }" : "=r"(a) : "l"(p));
    return a;
}
__device__ __forceinline__ uint32_t sw128(uint32_t o) { return o ^ ((o >> 3) & 0x70); }
__device__ __forceinline__ void split_bf(float v, bf& hi, bf& lo) {
    hi = __float2bfloat16(v);
    lo = __float2bfloat16(v - __bfloat162float(hi));
}
__device__ __forceinline__ void cpa_tile(uint32_t sdst, const bf* src, long ld, int t) {
#pragma unroll
    for (int r = 0; r < 4; r++) {
        const int it = t + r * 256;
        const int row = it >> 3, seg = it & 7;
        const uint32_t d = sdst + sw128(row * 128 + seg * 16);
        const bf* p = src + (size_t)row * ld + seg * 8;
        asm volatile("cp.async.cg.shared.global [%0], [%1], 16;" :: "r"(d), "l"(p));
    }
}
#define CPA_COMMIT() asm volatile("cp.async.commit_group;" ::: "memory")
#define CPA_WAIT2()  asm volatile("cp.async.wait_group 2;" ::: "memory")
#define CPA_WAIT1()  asm volatile("cp.async.wait_group 1;" ::: "memory")
#define CPA_WAIT0()  asm volatile("cp.async.wait_group 0;" ::: "memory")

#define MMA_CHUNK(sA, sB, ACC)                                                           \
    {                                                                                    \
        _Pragma("unroll")                                                                \
        for (int ks = 0; ks < 4; ks++) {                                                 \
            const int kb = ks * 32;                                                      \
            uint32_t a[4][4], bfr[4][2];                                                 \
            _Pragma("unroll")                                                            \
            for (int mi = 0; mi < 4; mi++) {                                             \
                const uint32_t addr = (sA) + sw128((warp_m * 64 + mi * 16 + (lane & 15)) * 128 \
                                                   + kb + (lane >> 4) * 16);             \
                asm volatile("ldmatrix.sync.aligned.m8n8.x4.shared.b16 {%0,%1,%2,%3}, [%4];" \
                    : "=r"(a[mi][0]), "=r"(a[mi][1]), "=r"(a[mi][2]), "=r"(a[mi][3]) : "r"(addr)); \
            }                                                                            \
            _Pragma("unroll")                                                            \
            for (int jp = 0; jp < 2; jp++) {                                             \
                const uint32_t addr = (sB) + sw128((warp_n * 32 + jp * 16 + ((lane >> 4) & 1) * 8 \
                                                    + (lane & 7)) * 128                  \
                                                   + kb + ((lane >> 3) & 1) * 16);       \
                asm volatile("ldmatrix.sync.aligned.m8n8.x4.shared.b16 {%0,%1,%2,%3}, [%4];" \
                    : "=r"(bfr[jp * 2][0]), "=r"(bfr[jp * 2][1]),                        \
                      "=r"(bfr[jp * 2 + 1][0]), "=r"(bfr[jp * 2 + 1][1]) : "r"(addr));   \
            }                                                                            \
            _Pragma("unroll")                                                            \
            for (int mi = 0; mi < 4; mi++)                                               \
                _Pragma("unroll")                                                        \
                for (int nj = 0; nj < 4; nj++)                                           \
                    asm volatile(                                                        \
                        "mma.sync.aligned.m16n8k16.row.col.f32.bf16.bf16.f32 "           \
                        "{%0,%1,%2,%3}, {%4,%5,%6,%7}, {%8,%9}, {%0,%1,%2,%3};"          \
                        : "+f"(ACC[mi][nj][0]), "+f"(ACC[mi][nj][1]),                    \
                          "+f"(ACC[mi][nj][2]), "+f"(ACC[mi][nj][3])                     \
                        : "r"(a[mi][0]), "r"(a[mi][1]), "r"(a[mi][2]), "r"(a[mi][3]),    \
                          "r"(bfr[nj][0]), "r"(bfr[nj][1]));                             \
        }                                                                                \
    }

// ---------------- shared 3-pass split mainloop (A,B stored hi|lo) ----------------
__device__ __forceinline__ void gemm_main(
    const bf* Ab, const bf* Bb, long lda, long ldb, long loA, long loB, int nchp,
    uint32_t smbase, int t, int lane, int warp_m, int warp_n, float (&acc)[4][4][4])
{
    const int nch = nchp * 3;
#define ACHUNK(j) (Ab + ((j) >= 2 * nchp ? loA : 0) + (size_t)((j) % nchp) * 64)
#define BCHUNK(j) (Bb + (((j) >= nchp && (j) < 2 * nchp) ? loB : 0) + (size_t)((j) % nchp) * 64)
    cpa_tile(smbase,         ACHUNK(0), lda, t);
    cpa_tile(smbase + 16384, BCHUNK(0), ldb, t);
    CPA_COMMIT();
    if (nch > 1) {
        cpa_tile(smbase + 32768, ACHUNK(1), lda, t);
        cpa_tile(smbase + 49152, BCHUNK(1), ldb, t);
    }
    CPA_COMMIT();
    for (int i = 0; i < nch; i++) {
        CPA_WAIT1();
        __syncthreads();
        const uint32_t sA = smbase + (i & 1) * 32768;
        MMA_CHUNK(sA, sA + 16384, acc);
        __syncthreads();
        if (i + 2 < nch) {
            cpa_tile(smbase + (i & 1) * 32768,         ACHUNK(i + 2), lda, t);
            cpa_tile(smbase + (i & 1) * 32768 + 16384, BCHUNK(i + 2), ldb, t);
        }
        CPA_COMMIT();
    }
    CPA_WAIT0();
#undef ACHUNK
#undef BCHUNK
}

#define STAGE_ACC(ACC, SCALE0, SCALE1)                                                   \
    if (warp_n == cb) {                                                                  \
        _Pragma("unroll")                                                                \
        for (int mi = 0; mi < 4; mi++)                                                   \
            _Pragma("unroll")                                                            \
            for (int nj = 0; nj < 4; nj++) {                                             \
                const int r  = warp_m * 64 + mi * 16 + (lane >> 2);                      \
                const int cc = nj * 8 + (lane & 3) * 2;                                  \
                stg[r * 33 + cc]           = ACC[mi][nj][0] * (SCALE0);                  \
                stg[r * 33 + cc + 1]       = ACC[mi][nj][1] * (SCALE0);                  \
                stg[(r + 8) * 33 + cc]     = ACC[mi][nj][2] * (SCALE1);                  \
                stg[(r + 8) * 33 + cc + 1] = ACC[mi][nj][3] * (SCALE1);                  \
            }                                                                            \
    }

// ---------------- merged QKV projection: grid (64, 8, 3) ----------------
struct PArgs {
    const bf *A0, *A1, *A2, *B0, *B1, *B2;
    const float *b0, *b1, *b2;
    bf *o0, *o1, *o2;
};

__global__ __launch_bounds__(256) void tc_projVKQ(PArgs g)
{
    extern __shared__ __align__(16) char smt[];
    const uint32_t smbase = smem_u32(smt);
    const int t = threadIdx.x, lane = t & 31, wid = t >> 5;
    const int warp_m = wid >> 2, warp_n = wid & 3;
    const int m0 = blockIdx.x * 128, n0 = blockIdx.y * 128;
    const int z = blockIdx.z;

    const bf* A = (z == 0 ? g.A0 : z == 1 ? g.A1 : g.A2) + (size_t)m0 * 2048;
    const bf* B = (z == 0 ? g.B0 : z == 1 ? g.B1 : g.B2) + (size_t)n0 * 2048;
    const float* bias = z == 0 ? g.b0 : z == 1 ? g.b1 : g.b2;
    bf* oc = z == 0 ? g.o0 : z == 1 ? g.o1 : g.o2;

    float acc[4][4][4];
#pragma unroll
    for (int i = 0; i < 4; i++)
#pragma unroll
        for (int j = 0; j < 4; j++)
#pragma unroll
            for (int c = 0; c < 4; c++) acc[i][j][c] = 0.f;

    gemm_main(A, B, 2048, 2048, 1024, 1024, 16, smbase, t, lane, warp_m, warp_n, acc);

    float* stg = (float*)smt;
    for (int cb = 0; cb < 4; cb++) {
        __syncthreads();
        STAGE_ACC(acc, 1.f, 1.f);
        __syncthreads();
        if (z == 0) {
            // V: transposed per-head [bh][d][2S] (hi|lo)
            const int dloc = t & 31, soff = (t >> 5) * 16;
            const int b = m0 >> 10, h = blockIdx.y, d = cb * 32 + dloc;
            const int scol = (m0 & 1023) + soff;
            bf hi16[16], lo16[16];
#pragma unroll
            for (int i2 = 0; i2 < 16; i2++) {
                float v = stg[(soff + i2) * 33 + dloc] + bias[n0 + d];
                split_bf(v, hi16[i2], lo16[i2]);
            }
            bf* dst = oc + ((size_t)(b * HSZ + h) * 128 + d) * 2048 + scol;
            uint4* hv = (uint4*)hi16; uint4* lv = (uint4*)lo16;
            *(uint4*)(dst) = hv[0];          *(uint4*)(dst + 8) = hv[1];
            *(uint4*)(dst + 1024) = lv[0];   *(uint4*)(dst + 1032) = lv[1];
        } else {
            // K/Q: head-split rows (hi|lo)
            const int row = t >> 1, c0 = (t & 1) * 16;
            const float* sr = stg + row * 33 + c0;
            const int h = blockIdx.y, m = m0 + row, b = m >> 10, s = m & 1023;
            const int d0 = cb * 32 + c0;
            bf* cd = oc + ((size_t)(b * HSZ + h) * SSZ + s) * 256 + d0;
            bf hi16[16], lo16[16];
#pragma unroll
            for (int c = 0; c < 16; c++)
                split_bf(sr[c] + bias[n0 + d0 + c], hi16[c], lo16[c]);
            uint4* hv = (uint4*)hi16; uint4* lv = (uint4*)lo16;
            *(uint4*)(cd) = hv[0];        *(uint4*)(cd + 8) = hv[1];
            *(uint4*)(cd + 128) = lv[0];  *(uint4*)(cd + 136) = lv[1];
        }
    }
}

// ---------------- merged gate GEMMs: grid (512, 1, 2) ----------------
struct G2Args {
    const bf *A0, *A1, *B0, *B1;
    const float *b0, *b1;
    float *o0, *o1;
};

__global__ __launch_bounds__(256) void tc_gate(G2Args g)
{
    extern __shared__ __align__(16) char smt[];
    const uint32_t smbase = smem_u32(smt);
    const int t = threadIdx.x, lane = t & 31, wid = t >> 5;
    const int warp_m = wid >> 2, warp_n = wid & 3;
    const int m0 = blockIdx.x * 128;
    const int z = blockIdx.z;

    const bf* A = (z ? g.A1 : g.A0) + (size_t)m0 * 256;
    const bf* B = z ? g.B1 : g.B0;
    const float* bias = z ? g.b1 : g.b0;
    float* of = z ? g.o1 : g.o0;

    float acc[4][4][4];
#pragma unroll
    for (int i = 0; i < 4; i++)
#pragma unroll
        for (int j = 0; j < 4; j++)
#pragma unroll
            for (int c = 0; c < 4; c++) acc[i][j][c] = 0.f;

    gemm_main(A, B, 256, 256, 128, 128, 2, smbase, t, lane, warp_m, warp_n, acc);

    float* stg = (float*)smt;
    for (int cb = 0; cb < 4; cb++) {
        __syncthreads();
        STAGE_ACC(acc, 1.f, 1.f);
        __syncthreads();
        const int row = t >> 1, c0 = (t & 1) * 16;
        const float* sr = stg + row * 33 + c0;
        float* fd = of + (size_t)(m0 + row) * 128 + cb * 32 + c0;
#pragma unroll
        for (int c = 0; c < 16; c += 4) {
            float4 w;
            w.x = sr[c]     + bias[cb * 32 + c0 + c];
            w.y = sr[c + 1] + bias[cb * 32 + c0 + c + 1];
            w.z = sr[c + 2] + bias[cb * 32 + c0 + c + 2];
            w.w = sr[c + 3] + bias[cb * 32 + c0 + c + 3];
            *(float4*)(fd + c) = w;
        }
    }
}

// ---------------- final projection: grid (64, 8) ----------------
__global__ __launch_bounds__(256) void tc_final(
    const bf* __restrict__ A, const bf* __restrict__ B,
    const float* __restrict__ bias, float* __restrict__ of)
{
    extern __shared__ __align__(16) char smt[];
    const uint32_t smbase = smem_u32(smt);
    const int t = threadIdx.x, lane = t & 31, wid = t >> 5;
    const int warp_m = wid >> 2, warp_n = wid & 3;
    const int m0 = blockIdx.x * 128, n0 = blockIdx.y * 128;

    float acc[4][4][4];
#pragma unroll
    for (int i = 0; i < 4; i++)
#pragma unroll
        for (int j = 0; j < 4; j++)
#pragma unroll
            for (int c = 0; c < 4; c++) acc[i][j][c] = 0.f;

    gemm_main(A + (size_t)m0 * 2048, B + (size_t)n0 * 2048,
              2048, 2048, 1024, 1024, 16, smbase, t, lane, warp_m, warp_n, acc);

    float* stg = (float*)smt;
    for (int cb = 0; cb < 4; cb++) {
        __syncthreads();
        STAGE_ACC(acc, 1.f, 1.f);
        __syncthreads();
        const int row = t >> 1, c0 = (t & 1) * 16;
        const float* sr = stg + row * 33 + c0;
        const int nt = n0 + cb * 32 + c0;
        float* fd = of + (size_t)(m0 + row) * 1024 + nt;
#pragma unroll
        for (int c = 0; c < 16; c += 4) {
            float4 w;
            w.x = sr[c]     + bias[nt + c];
            w.y = sr[c + 1] + bias[nt + c + 1];
            w.z = sr[c + 2] + bias[nt + c + 2];
            w.w = sr[c + 3] + bias[nt + c + 3];
            *(float4*)(fd + c) = w;
        }
    }
}

// ---------------- fused flash attention v3 (unchanged from R10) ----------------
#define FQB  0
#define FPB  65536
#define FSB  131072
#define FSM_PMAX 180224
#define FSM_PSUM (180224 + 2048)
#define FSM_MRUN (180224 + 4096)
#define FSM_LRUN (180224 + 4608)
#define FSM_MASK (180224 + 5120)
#define FSMEM    (180224 + 5376)

__global__ __launch_bounds__(256) void flash_att(
    const bf* __restrict__ qg, const bf* __restrict__ kg, const bf* __restrict__ vt,
    const unsigned char* __restrict__ mask, bf* __restrict__ ctx)
{
    extern __shared__ __align__(16) char smt[];
    const uint32_t smbase = smem_u32(smt);
    float* pmax = (float*)(smt + FSM_PMAX);
    float* psum = (float*)(smt + FSM_PSUM);
    float* m_run = (float*)(smt + FSM_MRUN);
    float* l_run = (float*)(smt + FSM_LRUN);
    unsigned char* mk = (unsigned char*)(smt + FSM_MASK);

    const int t = threadIdx.x, lane = t & 31, wid = t >> 5;
    const int warp_m = wid >> 2, warp_n = wid & 3;
    const int m0 = blockIdx.x * 128;
    const int bh = blockIdx.z, b = bh >> 3, h = bh & 7;

    const bf* Aq = qg + (size_t)bh * SSZ * 256 + (size_t)m0 * 256;
    const bf* Bk = kg + (size_t)bh * SSZ * 256;
    const bf* Vt = vt + (size_t)bh * 128 * 2048;

#pragma unroll
    for (int c = 0; c < 4; c++)
        cpa_tile(smbase + FQB + c * 16384, Aq + c * 64, 256, t);
    CPA_COMMIT();

    float oacc[4][4][4];
#pragma unroll
    for (int i = 0; i < 4; i++)
#pragma unroll
        for (int j = 0; j < 4; j++)
#pragma unroll
            for (int c = 0; c < 4; c++) oacc[i][j][c] = 0.f;

    if (t < 128) { m_run[t] = -1e30f; l_run[t] = 0.f; }
    CPA_WAIT0();
    __syncthreads();

    for (int kt = 0; kt < 8; kt++) {
        if (t < 128) mk[t] = mask[b * SSZ + kt * 128 + t];
        const bf* Bb = Bk + (size_t)(kt * 128) * 256;

        float sacc[4][4][4];
#pragma unroll
        for (int i = 0; i < 4; i++)
#pragma unroll
            for (int j = 0; j < 4; j++)
#pragma unroll
                for (int c = 0; c < 4; c++) sacc[i][j][c] = 0.f;

        cpa_tile(smbase + FSB,         Bb,       256, t); CPA_COMMIT();
        cpa_tile(smbase + FSB + 16384, Bb + 64,  256, t); CPA_COMMIT();
        cpa_tile(smbase + FSB + 32768, Bb + 128, 256, t); CPA_COMMIT();
        CPA_WAIT2(); __syncthreads();
        MMA_CHUNK(smbase + FQB,         smbase + FSB, sacc);
        MMA_CHUNK(smbase + FQB + 32768, smbase + FSB, sacc);
        __syncthreads();
        cpa_tile(smbase + FSB, Bb + 192, 256, t); CPA_COMMIT();
        CPA_WAIT2(); __syncthreads();
        MMA_CHUNK(smbase + FQB + 16384, smbase + FSB + 16384, sacc);
        MMA_CHUNK(smbase + FQB + 49152, smbase + FSB + 16384, sacc);
        CPA_WAIT1(); __syncthreads();
        MMA_CHUNK(smbase + FQB,         smbase + FSB + 32768, sacc);
        CPA_WAIT0(); __syncthreads();
        MMA_CHUNK(smbase + FQB + 16384, smbase + FSB, sacc);
        __syncthreads();

        const float scl = 0.08838834764831845f;
#pragma unroll
        for (int mi = 0; mi < 4; mi++)
#pragma unroll
            for (int nj = 0; nj < 4; nj++) {
                const int cbase = warp_n * 32 + nj * 8 + (lane & 3) * 2;
                const bool mk0 = mk[cbase] != 0, mk1 = mk[cbase + 1] != 0;
                sacc[mi][nj][0] = mk0 ? -1e9f : sacc[mi][nj][0] * scl;
                sacc[mi][nj][1] = mk1 ? -1e9f : sacc[mi][nj][1] * scl;
                sacc[mi][nj][2] = mk0 ? -1e9f : sacc[mi][nj][2] * scl;
                sacc[mi][nj][3] = mk1 ? -1e9f : sacc[mi][nj][3] * scl;
            }

#pragma unroll
        for (int mi = 0; mi < 4; mi++) {
            float mx0 = -1e30f, mx1 = -1e30f;
#pragma unroll
            for (int nj = 0; nj < 4; nj++) {
                mx0 = fmaxf(mx0, fmaxf(sacc[mi][nj][0], sacc[mi][nj][1]));
                mx1 = fmaxf(mx1, fmaxf(sacc[mi][nj][2], sacc[mi][nj][3]));
            }
            mx0 = fmaxf(mx0, __shfl_xor_sync(0xFFFFFFFFu, mx0, 1));
            mx0 = fmaxf(mx0, __shfl_xor_sync(0xFFFFFFFFu, mx0, 2));
            mx1 = fmaxf(mx1, __shfl_xor_sync(0xFFFFFFFFu, mx1, 1));
            mx1 = fmaxf(mx1, __shfl_xor_sync(0xFFFFFFFFu, mx1, 2));
            if ((lane & 3) == 0) {
                const int r = warp_m * 64 + mi * 16 + (lane >> 2);
                pmax[warp_n * 128 + r] = mx0;
                pmax[warp_n * 128 + r + 8] = mx1;
            }
        }
        __syncthreads();

        cpa_tile(smbase + FSB,          Vt + (size_t)kt * 128,        2048, t); CPA_COMMIT();
        cpa_tile(smbase + FSB + 16384,  Vt + (size_t)kt * 128 + 64,   2048, t); CPA_COMMIT();
        cpa_tile(smbase + FSB + 32768,  Vt + 1024 + (size_t)kt * 128, 2048, t); CPA_COMMIT();

#pragma unroll
        for (int mi = 0; mi < 4; mi++) {
            const int r0 = warp_m * 64 + mi * 16 + (lane >> 2), r1 = r0 + 8;
            const float mo0 = m_run[r0], mo1 = m_run[r1];
            float mn0 = fmaxf(fmaxf(pmax[r0], pmax[128 + r0]), fmaxf(pmax[256 + r0], pmax[384 + r0]));
            float mn1 = fmaxf(fmaxf(pmax[r1], pmax[128 + r1]), fmaxf(pmax[256 + r1], pmax[384 + r1]));
            mn0 = fmaxf(mn0, mo0); mn1 = fmaxf(mn1, mo1);
            const float f0 = __expf(mo0 - mn0), f1 = __expf(mo1 - mn1);
            float s0 = 0.f, s1 = 0.f;
#pragma unroll
            for (int nj = 0; nj < 4; nj++) {
                sacc[mi][nj][0] = __expf(sacc[mi][nj][0] - mn0); s0 += sacc[mi][nj][0];
                sacc[mi][nj][1] = __expf(sacc[mi][nj][1] - mn0); s0 += sacc[mi][nj][1];
                sacc[mi][nj][2] = __expf(sacc[mi][nj][2] - mn1); s1 += sacc[mi][nj][2];
                sacc[mi][nj][3] = __expf(sacc[mi][nj][3] - mn1); s1 += sacc[mi][nj][3];
                oacc[mi][nj][0] *= f0; oacc[mi][nj][1] *= f0;
                oacc[mi][nj][2] *= f1; oacc[mi][nj][3] *= f1;
            }
            s0 += __shfl_xor_sync(0xFFFFFFFFu, s0, 1); s0 += __shfl_xor_sync(0xFFFFFFFFu, s0, 2);
            s1 += __shfl_xor_sync(0xFFFFFFFFu, s1, 1); s1 += __shfl_xor_sync(0xFFFFFFFFu, s1, 2);
            if ((lane & 3) == 0) {
                psum[warp_n * 128 + r0] = s0;
                psum[warp_n * 128 + r1] = s1;
            }
        }
        __syncthreads();
        if (t < 128) {
            const float mo = m_run[t];
            float mn = fmaxf(fmaxf(pmax[t], pmax[128 + t]), fmaxf(pmax[256 + t], pmax[384 + t]));
            mn = fmaxf(mn, mo);
            l_run[t] = l_run[t] * __expf(mo - mn)
                     + psum[t] + psum[128 + t] + psum[256 + t] + psum[384 + t];
            m_run[t] = mn;
        }

        {
            const int hc = warp_n >> 1;
            char* pbh = smt + FPB + hc * 16384;
            char* pbl = smt + FPB + 32768 + hc * 16384;
#pragma unroll
            for (int mi = 0; mi < 4; mi++)
#pragma unroll
                for (int nj = 0; nj < 4; nj++) {
                    const int r0 = warp_m * 64 + mi * 16 + (lane >> 2);
                    const int lc = (warp_n & 1) * 32 + nj * 8 + (lane & 3) * 2;
                    __nv_bfloat162 h0, h1, l0v, l1v;
                    bf hh, ll;
                    split_bf(sacc[mi][nj][0], hh, ll); h0.x = hh; l0v.x = ll;
                    split_bf(sacc[mi][nj][1], hh, ll); h0.y = hh; l0v.y = ll;
                    split_bf(sacc[mi][nj][2], hh, ll); h1.x = hh; l1v.x = ll;
                    split_bf(sacc[mi][nj][3], hh, ll); h1.y = hh; l1v.y = ll;
                    *(__nv_bfloat162*)(pbh + sw128(r0 * 128 + lc * 2)) = h0;
                    *(__nv_bfloat162*)(pbh + sw128((r0 + 8) * 128 + lc * 2)) = h1;
                    *(__nv_bfloat162*)(pbl + sw128(r0 * 128 + lc * 2)) = l0v;
                    *(__nv_bfloat162*)(pbl + sw128((r0 + 8) * 128 + lc * 2)) = l1v;
                }
        }
        __syncthreads();

        CPA_WAIT2(); __syncthreads();
        MMA_CHUNK(smbase + FPB,          smbase + FSB, oacc);
        MMA_CHUNK(smbase + FPB + 32768,  smbase + FSB, oacc);
        __syncthreads();
        cpa_tile(smbase + FSB, Vt + 1024 + (size_t)kt * 128 + 64, 2048, t);
        CPA_COMMIT();
        CPA_WAIT2(); __syncthreads();
        MMA_CHUNK(smbase + FPB + 16384,  smbase + FSB + 16384, oacc);
        MMA_CHUNK(smbase + FPB + 49152,  smbase + FSB + 16384, oacc);
        CPA_WAIT1(); __syncthreads();
        MMA_CHUNK(smbase + FPB,          smbase + FSB + 32768, oacc);
        CPA_WAIT0(); __syncthreads();
        MMA_CHUNK(smbase + FPB + 16384,  smbase + FSB, oacc);
        __syncthreads();
    }

    float inv0[4], inv1[4];
#pragma unroll
    for (int mi = 0; mi < 4; mi++) {
        const int r0 = warp_m * 64 + mi * 16 + (lane >> 2);
        inv0[mi] = 1.f / l_run[r0];
        inv1[mi] = 1.f / l_run[r0 + 8];
    }
    float* stg = (float*)smt;
    for (int cb = 0; cb < 4; cb++) {
        __syncthreads();
        STAGE_ACC(oacc, inv0[mi], inv1[mi]);
        __syncthreads();
        const int row = t >> 1, c0 = (t & 1) * 16;
        const float* sr = stg + row * 33 + c0;
        const int n = cb * 32 + c0;
        bf* cd = ctx + ((size_t)b * SSZ + m0 + row) * 2048 + h * 128 + n;
        bf hi16[16], lo16[16];
#pragma unroll
        for (int c = 0; c < 16; c++) split_bf(sr[c], hi16[c], lo16[c]);
        uint4* hv = (uint4*)hi16; uint4* lv = (uint4*)lo16;
        *(uint4*)(cd) = hv[0];          *(uint4*)(cd + 8) = hv[1];
        *(uint4*)(cd + 1024) = lv[0];   *(uint4*)(cd + 1032) = lv[1];
    }
}

// ---------------- prep kernels ----------------
__global__ __launch_bounds__(256) void split_act(const float* v, const float* k, const float* q)
{
    const float* s = blockIdx.z == 0 ? v : blockIdx.z == 1 ? k : q;
    bf* dst = g_xc[blockIdx.z];
    const size_t i = ((size_t)blockIdx.x * 256 + threadIdx.x) * 4;
    const size_t row = i >> 10, col = i & 1023;
    float4 x = *(const float4*)(s + i);
    bf h[4], l[4];
    split_bf(x.x, h[0], l[0]); split_bf(x.y, h[1], l[1]);
    split_bf(x.z, h[2], l[2]); split_bf(x.w, h[3], l[3]);
    bf* d = dst + row * 2048 + col;
    *(uint2*)(d) = *(uint2*)h;
    *(uint2*)(d + 1024) = *(uint2*)l;
}

__global__ void wsplit(const float* W, bf* Wc, int K, int N)
{
    __shared__ float sm[32][33];
    const int k0 = blockIdx.y * 32, n0 = blockIdx.x * 32;
    for (int r = threadIdx.y; r < 32; r += 8)
        sm[r][threadIdx.x] = W[(size_t)(k0 + r) * N + n0 + threadIdx.x];
    __syncthreads();
    for (int r = threadIdx.y; r < 32; r += 8) {
        bf hi, lo; split_bf(sm[threadIdx.x][r], hi, lo);
        bf* d = Wc + (size_t)(n0 + r) * 2 * K + k0 + threadIdx.x;
        d[0] = hi; d[K] = lo;
    }
}

__global__ __launch_bounds__(128) void gate_apply(const float* Wg2, const float* bg2)
{
    const size_t row = blockIdx.x;
    const int d = threadIdx.x;
    const size_t o = row * 128 + d;
    float tv = g_gx[o] * g_gy[o];
    float s0 = tv * Wg2[d * 2], s1 = tv * Wg2[d * 2 + 1];
    const int lane = d & 31, w = d >> 5;
#pragma unroll
    for (int off = 16; off; off >>= 1) {
        s0 += __shfl_xor_sync(0xFFFFFFFFu, s0, off);
        s1 += __shfl_xor_sync(0xFFFFFFFFu, s1, off);
    }
    __shared__ float r0[4], r1[4];
    if (lane == 0) { r0[w] = s0; r1[w] = s1; }
    __syncthreads();
    float t0 = r0[0] + r0[1] + r0[2] + r0[3];
    float t1 = r1[0] + r1[1] + r1[2] + r1[3];
    float gk = 1.f / (1.f + __expf(-(t0 + bg2[0])));
    float gq = 1.f / (1.f + __expf(-(t1 + bg2[1])));
    const size_t rb = row * 256 + d;
    float kv = __bfloat162float(g_khc[rb]) + __bfloat162float(g_khc[rb + 128]);
    float qv = __bfloat162float(g_qhc[rb]) + __bfloat162float(g_qhc[rb + 128]);
    bf hi, lo;
    split_bf(kv * gk, hi, lo);
    g_kgc[rb] = hi; g_kgc[rb + 128] = lo;
    split_bf(qv * gq, hi, lo);
    g_qgc[rb] = hi; g_qgc[rb + 128] = lo;
}

// ---------------- launch ----------------
#define TCSMEM 65536

extern "C" void kernel_launch(void* const* d_in, const int* in_sizes, int n_in,
                              void* d_out, int out_size)
{
    (void)in_sizes; (void)n_in; (void)out_size;
    const float* v  = (const float*)d_in[0];
    const float* k  = (const float*)d_in[1];
    const float* q  = (const float*)d_in[2];
    const unsigned char* mask = (const unsigned char*)d_in[3];
    const float* Wv = (const float*)d_in[4];  const float* bv = (const float*)d_in[5];
    const float* Wk = (const float*)d_in[6];  const float* bk = (const float*)d_in[7];
    const float* Wq = (const float*)d_in[8];  const float* bq = (const float*)d_in[9];
    const float* Wm = (const float*)d_in[10]; const float* bm = (const float*)d_in[11];
    const float* WgX = (const float*)d_in[12]; const float* bgX = (const float*)d_in[13];
    const float* WgY = (const float*)d_in[14]; const float* bgY = (const float*)d_in[15];
    const float* Wg2 = (const float*)d_in[16]; const float* bg2 = (const float*)d_in[17];
    float* outp = (float*)d_out;

    cudaFuncSetAttribute(tc_projVKQ, cudaFuncAttributeMaxDynamicSharedMemorySize, TCSMEM);
    cudaFuncSetAttribute(tc_gate,    cudaFuncAttributeMaxDynamicSharedMemorySize, TCSMEM);
    cudaFuncSetAttribute(tc_final,   cudaFuncAttributeMaxDynamicSharedMemorySize, TCSMEM);
    cudaFuncSetAttribute(flash_att,  cudaFuncAttributeMaxDynamicSharedMemorySize, FSMEM);

    bf* wc0; bf* wc1; bf* wc2; bf* wc3; bf* wg0; bf* wg1;
    bf* xc0; bf* xc1; bf* xc2;
    cudaGetSymbolAddress((void**)&wc0, g_wc);  wc1 = wc0 + (size_t)1024 * 2048;
    wc2 = wc1 + (size_t)1024 * 2048; wc3 = wc2 + (size_t)1024 * 2048;
    cudaGetSymbolAddress((void**)&wg0, g_wgc); wg1 = wg0 + (size_t)128 * 256;
    cudaGetSymbolAddress((void**)&xc0, g_xc);  xc1 = xc0 + (size_t)MT * 2048; xc2 = xc1 + (size_t)MT * 2048;
    float *gx, *gy;
    bf *khc, *qhc, *kgc, *qgc, *vtc, *ctxc;
    cudaGetSymbolAddress((void**)&gx, g_gx);   cudaGetSymbolAddress((void**)&gy, g_gy);
    cudaGetSymbolAddress((void**)&khc, g_khc); cudaGetSymbolAddress((void**)&qhc, g_qhc);
    cudaGetSymbolAddress((void**)&kgc, g_kgc); cudaGetSymbolAddress((void**)&qgc, g_qgc);
    cudaGetSymbolAddress((void**)&vtc, g_vtc); cudaGetSymbolAddress((void**)&ctxc, g_ctxc);

    split_act<<<dim3(8192, 1, 3), 256>>>(v, k, q);
    wsplit<<<dim3(32, 32), dim3(32, 8)>>>(Wv, wc0, 1024, 1024);
    wsplit<<<dim3(32, 32), dim3(32, 8)>>>(Wk, wc1, 1024, 1024);
    wsplit<<<dim3(32, 32), dim3(32, 8)>>>(Wq, wc2, 1024, 1024);
    wsplit<<<dim3(32, 32), dim3(32, 8)>>>(Wm, wc3, 1024, 1024);
    wsplit<<<dim3(4, 4),   dim3(32, 8)>>>(WgX, wg0, 128, 128);
    wsplit<<<dim3(4, 4),   dim3(32, 8)>>>(WgY, wg1, 128, 128);

    // merged V/K/Q projection (one launch, 1536 CTAs)
    PArgs p = {};
    p.A0 = xc0; p.A1 = xc1; p.A2 = xc2;
    p.B0 = wc0; p.B1 = wc1; p.B2 = wc2;
    p.b0 = bv;  p.b1 = bk;  p.b2 = bq;
    p.o0 = vtc; p.o1 = khc; p.o2 = qhc;
    tc_projVKQ<<<dim3(64, 8, 3), 256, TCSMEM>>>(p);

    // merged gate GEMMs (one launch, 1024 CTAs)
    G2Args gg = {};
    gg.A0 = khc; gg.A1 = qhc;
    gg.B0 = wg0; gg.B1 = wg1;
    gg.b0 = bgX; gg.b1 = bgY;
    gg.o0 = gx;  gg.o1 = gy;
    tc_gate<<<dim3(512, 1, 2), 256, TCSMEM>>>(gg);

    gate_apply<<<BHZ * SSZ, 128>>>(Wg2, bg2);

    flash_att<<<dim3(8, 1, BHZ), 256, FSMEM>>>(qgc, kgc, vtc, mask, ctxc);

    tc_final<<<dim3(64, 8), 256, TCSMEM>>>(ctxc, wc3, bm, outp);
}